// round 12
// baseline (speedup 1.0000x reference)
#include <cuda_runtime.h>
#include <cstdint>
#include <cstddef>

#define M_TOK 8192
#define Dm    512
#define Kcb   8192
#define Ff    129
#define Cc    64

// ---- int8 quantization (z, e ~ N(0,1); max|.| ~ 5.5 over 4.2M samples) ----
#define QRANGE 6.0f
#define QSCALE (127.0f / QRANGE)          // fp32 -> int8
#define DEQ2   (2.0f * (QRANGE / 127.0f) * (QRANGE / 127.0f))  // 2*sz*se

// ---- MMA kernel geometry: 128-thread CTAs, 2 CTAs/SM, int8 ----
#define NSPLIT      4
#define CODES_SPLIT (Kcb / NSPLIT)      // 2048
#define NCHUNK      128                 // codes per chunk
#define CHUNKS      (CODES_SPLIT / NCHUNK) // 16
#define KTOT        512                 // int8 k per row
#define KSTG        128                 // int8 per stage (128B row)
#define STG_CHUNK   (KTOT / KSTG)       // 4
#define G_TOT       (CHUNKS * STG_CHUNK)// 64
#define A_BYTES     16384               // 128 x 128 int8
#define B_BYTES     16384               // 128 x 128 int8
#define STAGE_BYTES (A_BYTES + B_BYTES) // 32768
#define SMEM_SZ     (3 * STAGE_BYTES)   // 98304 (2 CTAs/SM -> 192KB)
#define NCAND       2                   // top-2 per split, 4 splits -> 8 rechecked

// ---- scratch ----
__device__ float  g_z[M_TOK * Dm];
__device__ __align__(16) int8_t g_zq[M_TOK * KTOT];
__device__ __align__(16) int8_t g_eq[Kcb * KTOT];
__device__ float  g_e2[Kcb];
__device__ int    g_cand[NSPLIT * M_TOK * NCAND];
__device__ float  g_loss;

// ---- PTX helpers (generic sm_80-class; valid under compute_103) ----
__device__ __forceinline__ uint32_t smem_u32(const void* p) {
    uint32_t r;
    asm("{ .reg .u64 t; cvta.to.shared.u64 t, %1; cvt.u32.u64 %0, t; }" : "=r"(r) : "l"(p));
    return r;
}
#define CP_ASYNC16(dst, src) \
    asm volatile("cp.async.cg.shared.global [%0], [%1], 16;" :: "r"(dst), "l"(src))
#define CP_COMMIT() asm volatile("cp.async.commit_group;" ::: "memory")
#define CP_WAIT0()  asm volatile("cp.async.wait_group 0;" ::: "memory")
#define CP_WAIT1()  asm volatile("cp.async.wait_group 1;" ::: "memory")

#define LDSM4(r0, r1, r2, r3, a) \
    asm volatile("ldmatrix.sync.aligned.m8n8.x4.shared.b16 {%0,%1,%2,%3}, [%4];" \
        : "=r"(r0), "=r"(r1), "=r"(r2), "=r"(r3) : "r"(a))

// s8 IMMA: D(s32)[16x8] += A(s8)[16x32] * B(s8)[8x32]
#define IMMA16832(d, a0, a1, a2, a3, b0, b1) \
    asm volatile("mma.sync.aligned.m16n8k32.row.col.s32.s8.s8.s32 " \
        "{%0,%1,%2,%3}, {%4,%5,%6,%7}, {%8,%9}, {%0,%1,%2,%3};" \
        : "+r"((d)[0]), "+r"((d)[1]), "+r"((d)[2]), "+r"((d)[3]) \
        : "r"(a0), "r"(a1), "r"(a2), "r"(a3), "r"(b0), "r"(b1))

__device__ __forceinline__ bool score_less(float s, int k, float S, int K) {
    return s < S || (s == S && k < K);
}
__device__ __forceinline__ void top2_upd(float& s1, int& k1, float& s2, int& k2,
                                         float s, int k) {
    if (score_less(s, k, s1, k1)) { s2 = s1; k2 = k1; s1 = s; k1 = k; }
    else if (score_less(s, k, s2, k2)) { s2 = s; k2 = k; }
}
__device__ __forceinline__ int8_t q8(float v) {
    float s = v * QSCALE;
    s = fminf(fmaxf(s, -127.f), 127.f);
    return (int8_t)__float2int_rn(s);
}

// ===== kernel 1 (fused): codebook prep (blocks 0..1023) + zgemm (1024..1279) =====
__global__ __launch_bounds__(256) void k_prep_z(const float* __restrict__ x,
                                                const float* __restrict__ W,
                                                const float* __restrict__ b,
                                                const float* __restrict__ cb) {
    __shared__ float xs[32][Ff];
    if (blockIdx.x < 1024) {
        // ---- prep: e2 + int8 codebook ----
        int row  = blockIdx.x * 8 + (threadIdx.x >> 5);
        int lane = threadIdx.x & 31;
        const float* r = cb + (size_t)row * Dm;
        float s = 0.f;
        for (int i = lane; i < Dm; i += 32) {
            float v = r[i];
            g_eq[(size_t)row * KTOT + i] = q8(v);
            s = fmaf(v, v, s);
        }
        #pragma unroll
        for (int o = 16; o; o >>= 1) s += __shfl_xor_sync(0xffffffffu, s, o);
        if (lane == 0) g_e2[row] = s;
        if (blockIdx.x == 0 && threadIdx.x == 0) g_loss = 0.f;
        return;
    }
    // ---- zgemm: z = x @ W + b (fp32 + int8 copies) ----
    const int m0 = (blockIdx.x - 1024) * 32;
    const int t  = threadIdx.x;
    for (int i = t; i < 32 * Ff; i += 256) {
        int r = i / Ff, c = i - r * Ff;
        xs[r][c] = x[(m0 + r) * Ff + c];
    }
    __syncthreads();
    float acc0[32], acc1[32];
    const float b0 = b[t], b1 = b[t + 256];
    #pragma unroll
    for (int i = 0; i < 32; i++) { acc0[i] = b0; acc1[i] = b1; }
    float w0 = W[t], w1 = W[t + 256];
    for (int f = 0; f < Ff; f++) {
        float nw0 = 0.f, nw1 = 0.f;
        if (f + 1 < Ff) { nw0 = W[(f + 1) * Dm + t]; nw1 = W[(f + 1) * Dm + t + 256]; }
        #pragma unroll
        for (int i = 0; i < 32; i++) {
            float xv = xs[i][f];
            acc0[i] = fmaf(xv, w0, acc0[i]);
            acc1[i] = fmaf(xv, w1, acc1[i]);
        }
        w0 = nw0; w1 = nw1;
    }
    #pragma unroll
    for (int i = 0; i < 32; i++) {
        size_t zb = (size_t)(m0 + i) * Dm;
        g_z[zb + t] = acc0[i]; g_z[zb + t + 256] = acc1[i];
        size_t qb = (size_t)(m0 + i) * KTOT;
        g_zq[qb + t]       = q8(acc0[i]);
        g_zq[qb + t + 256] = q8(acc1[i]);
    }
}

// ===== kernel 2: IMMA int8 distance GEMM, 128-thr CTA, 2 CTAs/SM =====
// CTA tile: 128 tokens x 128 codes per chunk. Warp grid 2(M) x 2(N),
// warp tile 64x64. Rows = 128 int8 (128B); XOR swizzle
// off = row*128 + ((c16 ^ (row&7)) << 4), c16 = 16B chunk (0..7).
__device__ __forceinline__ void load_stage(int gg, uint32_t sb, int t,
                                           int m0, int split) {
    const int ch = gg >> 2;          // code chunk
    const int st = gg & 3;           // K stage in chunk
    const int d0 = st * KSTG;
    const int c0 = split * CODES_SPLIT + ch * NCHUNK;
    const uint32_t aB = sb, bB = sb + A_BYTES;
    #pragma unroll
    for (int i = 0; i < 8; i++) {    // A: 1024 x 16B
        int li = t + i * 128, row = li >> 3, c = li & 7;
        uint32_t sw = (uint32_t)(row * 128) + (uint32_t)(((c ^ (row & 7)) << 4));
        CP_ASYNC16(aB + sw, g_zq + (size_t)(m0 + row) * KTOT + d0 + c * 16);
    }
    #pragma unroll
    for (int i = 0; i < 8; i++) {    // B: 1024 x 16B
        int li = t + i * 128, row = li >> 3, c = li & 7;
        uint32_t sw = (uint32_t)(row * 128) + (uint32_t)(((c ^ (row & 7)) << 4));
        CP_ASYNC16(bB + sw, g_eq + (size_t)(c0 + row) * KTOT + d0 + c * 16);
    }
    CP_COMMIT();
}

__global__ __launch_bounds__(128, 2) void k_mma() {
    extern __shared__ __align__(16) char smem[];
    const uint32_t sb = smem_u32(smem);

    const int t = threadIdx.x;
    const int l = t & 31, wid = t >> 5;
    const int wm = wid & 1, wn = wid >> 1;       // 2 x 2 warp grid
    const int m0 = blockIdx.x * 128;
    const int split = blockIdx.y;
    const int l7 = l & 7, hi = (l >> 4) & 1, l15 = l & 15;

    uint32_t aBase[4], bBase[4];
    #pragma unroll
    for (int g4 = 0; g4 < 4; g4++) {
        aBase[g4] = (uint32_t)((wm * 64 + g4 * 16 + l15) * 128);
        bBase[g4] = (uint32_t)((wn * 64 + g4 * 16 + l15) * 128);
    }

    load_stage(0, sb + 0 * STAGE_BYTES, t, m0, split);
    load_stage(1, sb + 1 * STAGE_BYTES, t, m0, split);

    const float INF = __int_as_float(0x7f800000);
    float r1s[8], r2s[8]; int r1k[8], r2k[8];
    #pragma unroll
    for (int i = 0; i < 8; i++) { r1s[i] = INF; r2s[i] = INF; r1k[i] = 0x7fffffff; r2k[i] = 0x7fffffff; }

    int bufC = 0, bufP = 2;
    for (int ch = 0; ch < CHUNKS; ch++) {
        int acc[4][8][4];
        #pragma unroll
        for (int mt = 0; mt < 4; mt++)
            #pragma unroll
            for (int nt = 0; nt < 8; nt++)
                #pragma unroll
                for (int j = 0; j < 4; j++) acc[mt][nt][j] = 0;

        for (int st = 0; st < STG_CHUNK; st++) {
            const int g = ch * STG_CHUNK + st;
            if (g == G_TOT - 1) CP_WAIT0(); else CP_WAIT1();
            __syncthreads();
            if (g + 2 < G_TOT)
                load_stage(g + 2, sb + (uint32_t)bufP * STAGE_BYTES, t, m0, split);

            const uint32_t aO = sb + (uint32_t)bufC * STAGE_BYTES;
            const uint32_t bO = aO + A_BYTES;
            // 4 k32 steps per 128B row: step ks uses 16B cols ks*2 (k 0-15) and
            // ks*2+1 (k 16-31); lanes 16-31 (hi=1) fetch the +16B tile -> regs
            // map exactly to s8 m16n8k32 fragments {a0,a1,a2,a3} / {b0,b2|b1,b3}.
            #pragma unroll
            for (int ks = 0; ks < 4; ks++) {
                const uint32_t xv = (uint32_t)((((ks * 2) + hi) ^ l7) << 4);
                uint32_t a[4][4], b[4][4];
                #pragma unroll
                for (int g4 = 0; g4 < 4; g4++)
                    LDSM4(a[g4][0], a[g4][1], a[g4][2], a[g4][3], aO + aBase[g4] + xv);
                #pragma unroll
                for (int g4 = 0; g4 < 4; g4++)
                    LDSM4(b[g4][0], b[g4][1], b[g4][2], b[g4][3], bO + bBase[g4] + xv);
                #pragma unroll
                for (int mt = 0; mt < 4; mt++)
                    #pragma unroll
                    for (int p = 0; p < 4; p++) {
                        IMMA16832(acc[mt][2 * p],     a[mt][0], a[mt][1], a[mt][2], a[mt][3],
                                  b[p][0], b[p][2]);
                        IMMA16832(acc[mt][2 * p + 1], a[mt][0], a[mt][1], a[mt][2], a[mt][3],
                                  b[p][1], b[p][3]);
                    }
            }
            bufC = (bufC == 2) ? 0 : bufC + 1;
            bufP = (bufP == 2) ? 0 : bufP + 1;
        }

        // chunk epilogue: score = e2 - DEQ2 * dot_int, fold into running top-2
        const int cb0 = split * CODES_SPLIT + ch * NCHUNK + wn * 64 + (l & 3) * 2;
        #pragma unroll
        for (int mt = 0; mt < 4; mt++) {
            #pragma unroll
            for (int h = 0; h < 2; h++) {
                const int ri = mt * 2 + h;
                #pragma unroll
                for (int nt = 0; nt < 8; nt++) {
                    int k0 = cb0 + nt * 8;
                    float e20 = g_e2[k0], e21 = g_e2[k0 + 1];
                    float s0 = fmaf(-DEQ2, (float)acc[mt][nt][h * 2 + 0], e20);
                    float s1 = fmaf(-DEQ2, (float)acc[mt][nt][h * 2 + 1], e21);
                    top2_upd(r1s[ri], r1k[ri], r2s[ri], r2k[ri], s0, k0);
                    top2_upd(r1s[ri], r1k[ri], r2s[ri], r2k[ri], s1, k0 + 1);
                }
            }
        }
    }

    // ---- final merge: 16 values per token row -> top-2 candidates ----
    __syncthreads();
    float* sS = (float*)smem;                 // [128][16] floats (8 KB)
    int*   sK = (int*)(smem + 128 * 16 * 4);  // [128][16] ints  (8 KB)
    const int slot = (wn * 4 + (l & 3)) * 2;
    #pragma unroll
    for (int mt = 0; mt < 4; mt++) {
        #pragma unroll
        for (int h = 0; h < 2; h++) {
            int ri = mt * 2 + h;
            int row = wm * 64 + mt * 16 + h * 8 + (l >> 2);
            sS[row * 16 + slot]     = r1s[ri];
            sS[row * 16 + slot + 1] = r2s[ri];
            sK[row * 16 + slot]     = r1k[ri];
            sK[row * 16 + slot + 1] = r2k[ri];
        }
    }
    __syncthreads();
    {
        float b1 = INF, b2 = INF; int i1 = 0x7fffffff, i2 = 0x7fffffff;
        #pragma unroll
        for (int j = 0; j < 16; j++) {
            float s = sS[t * 16 + j]; int k = sK[t * 16 + j];
            top2_upd(b1, i1, b2, i2, s, k);
        }
        g_cand[((size_t)split * M_TOK + m0 + t) * NCAND + 0] = i1;
        g_cand[((size_t)split * M_TOK + m0 + t) * NCAND + 1] = i2;
    }
}

// ===== kernel 3: exact recheck of 8 candidates, gather, out, loss =====
__global__ __launch_bounds__(256) void k_out(const float* __restrict__ cb,
                                             const float* __restrict__ pos,
                                             float* __restrict__ out) {
    const int m = blockIdx.x, t = threadIdx.x;
    const int w = t >> 5, lane = t & 31;
    __shared__ int scand[8];
    __shared__ float sdot[8];
    __shared__ int sBest;
    __shared__ float red[8];

    if (t < 8)
        scand[t] = g_cand[((size_t)(t >> 1) * M_TOK + m) * NCAND + (t & 1)];
    __syncthreads();

    const float* zr = g_z + (size_t)m * Dm;
    const int cidx = scand[w];
    const float* cr = cb + (size_t)cidx * Dm;
    float p = 0.f;
    #pragma unroll
    for (int i = 0; i < 16; i++) {
        int d = lane + i * 32;
        p = fmaf(zr[d], cr[d], p);
    }
    #pragma unroll
    for (int o = 16; o; o >>= 1) p += __shfl_xor_sync(0xffffffffu, p, o);
    if (lane == 0) sdot[w] = p;
    __syncthreads();

    if (t == 0) {
        float bsc = 3.4e38f; int bi = 0x7fffffff;
        #pragma unroll
        for (int q = 0; q < 8; q++) {
            int k = scand[q];
            float sc = fmaf(-2.f, sdot[q], g_e2[k]);
            if (sc < bsc || (sc == bsc && k < bi)) { bsc = sc; bi = k; }
        }
        sBest = bi;
    }
    __syncthreads();

    const int idx = sBest;
    const float* q  = cb  + (size_t)idx * Dm;
    const float* pr = pos + (m & (Cc - 1)) * Dm;
    float lsum = 0.f;
    #pragma unroll
    for (int r = 0; r < 2; r++) {
        int d = t + r * 256;
        float qv = q[d], zv = zr[d];
        out[(size_t)m * Dm + d] = qv + pr[d];
        float df = qv - zv;
        lsum = fmaf(df, df, lsum);
    }
    #pragma unroll
    for (int o = 16; o; o >>= 1) lsum += __shfl_xor_sync(0xffffffffu, lsum, o);
    if (lane == 0) red[w] = lsum;
    __syncthreads();
    if (t == 0) {
        float s = 0.f;
        #pragma unroll
        for (int ww = 0; ww < 8; ww++) s += red[ww];
        atomicAdd(&g_loss, s);
    }
}

// ===== kernel 4: write commit_loss scalar =====
__global__ void k_final(float* __restrict__ out, int out_size) {
    if (out_size > M_TOK * Dm)
        out[M_TOK * Dm] = g_loss * (1.f / (float)((long)M_TOK * Dm));
}

// ===== launcher =====
extern "C" void kernel_launch(void* const* d_in, const int* in_sizes, int n_in,
                              void* d_out, int out_size) {
    const float* x   = (const float*)d_in[0];
    const float* W   = (const float*)d_in[1];
    const float* b   = (const float*)d_in[2];
    const float* cb  = (const float*)d_in[3];
    const float* pos = (const float*)d_in[4];
    float* out = (float*)d_out;

    cudaFuncSetAttribute(k_mma, cudaFuncAttributeMaxDynamicSharedMemorySize, SMEM_SZ);

    k_prep_z<<<1024 + M_TOK / 32, 256>>>(x, W, b, cb);
    k_mma   <<<dim3(M_TOK / 128, NSPLIT), 128, SMEM_SZ>>>();
    k_out   <<<M_TOK, 256>>>(cb, pos, out);
    k_final <<<1, 1>>>(out, out_size);
}

// round 13
// speedup vs baseline: 2.1052x; 2.1052x over previous
#include <cuda_runtime.h>
#include <cuda_fp16.h>
#include <cstdint>
#include <cstddef>

#define M_TOK 8192
#define Dm    512
#define Kcb   8192
#define Ff    129
#define Cc    64

// ---- MMA kernel geometry: 128-thread CTAs, 2 CTAs/SM ----
#define NSPLIT      4
#define CODES_SPLIT (Kcb / NSPLIT)      // 2048
#define NCHUNK      128                 // codes per chunk
#define CHUNKS      (CODES_SPLIT / NCHUNK) // 16
#define KTOT        512                 // fp16 z depth
#define KSTG        64                  // fp16 per stage
#define STG_CHUNK   (KTOT / KSTG)       // 8
#define G_TOT       (CHUNKS * STG_CHUNK)// 128
#define A_BYTES     16384               // 128 x 64 halfs
#define B_BYTES     16384               // 128 x 64 halfs
#define STAGE_BYTES (A_BYTES + B_BYTES) // 32768
#define SMEM_SZ     (3 * STAGE_BYTES)   // 98304 (2 CTAs/SM -> 192KB)
#define NCAND       2                   // top-2 per split, 4 splits -> 8 rechecked

// ---- scratch ----
__device__ float  g_z[M_TOK * Dm];
__device__ __align__(16) __half g_zc[M_TOK * KTOT];
__device__ __align__(16) __half g_e16[Kcb * Dm];
__device__ float  g_e2[Kcb];
__device__ int    g_cand[NSPLIT * M_TOK * NCAND];
__device__ float  g_loss;
__device__ unsigned g_done;

// ---- PTX helpers (generic sm_80-class; valid under compute_103) ----
__device__ __forceinline__ uint32_t smem_u32(const void* p) {
    uint32_t r;
    asm("{ .reg .u64 t; cvta.to.shared.u64 t, %1; cvt.u32.u64 %0, t; }" : "=r"(r) : "l"(p));
    return r;
}
#define CP_ASYNC16(dst, src) \
    asm volatile("cp.async.cg.shared.global [%0], [%1], 16;" :: "r"(dst), "l"(src))
#define CP_COMMIT() asm volatile("cp.async.commit_group;" ::: "memory")
#define CP_WAIT0()  asm volatile("cp.async.wait_group 0;" ::: "memory")
#define CP_WAIT1()  asm volatile("cp.async.wait_group 1;" ::: "memory")

#define LDSM4(r0, r1, r2, r3, a) \
    asm volatile("ldmatrix.sync.aligned.m8n8.x4.shared.b16 {%0,%1,%2,%3}, [%4];" \
        : "=r"(r0), "=r"(r1), "=r"(r2), "=r"(r3) : "r"(a))

#define MMA16816(d, a0, a1, a2, a3, b0, b1) \
    asm volatile("mma.sync.aligned.m16n8k16.row.col.f32.f16.f16.f32 " \
        "{%0,%1,%2,%3}, {%4,%5,%6,%7}, {%8,%9}, {%0,%1,%2,%3};" \
        : "+f"((d)[0]), "+f"((d)[1]), "+f"((d)[2]), "+f"((d)[3]) \
        : "r"(a0), "r"(a1), "r"(a2), "r"(a3), "r"(b0), "r"(b1))

// hot-path top-2: no index tie-break (exact recheck re-applies reference
// tie-break on the candidate set; equal-score near-minima land in (s1,s2)).
__device__ __forceinline__ void top2_upd(float& s1, int& k1, float& s2, int& k2,
                                         float s, int k) {
    if (s < s1) { s2 = s1; k2 = k1; s1 = s; k1 = k; }
    else if (s < s2) { s2 = s; k2 = k; }
}

// ===== kernel 1 (fused): codebook prep (blocks 0..1023) + zgemm (1024..1279) =====
__global__ __launch_bounds__(256) void k_prep_z(const float* __restrict__ x,
                                                const float* __restrict__ W,
                                                const float* __restrict__ b,
                                                const float* __restrict__ cb) {
    __shared__ float xs[32][Ff];
    if (blockIdx.x < 1024) {
        int row  = blockIdx.x * 8 + (threadIdx.x >> 5);
        int lane = threadIdx.x & 31;
        const float* r = cb + (size_t)row * Dm;
        float s = 0.f;
        for (int i = lane; i < Dm; i += 32) {
            float v = r[i];
            g_e16[(size_t)row * Dm + i] = __float2half_rn(v);
            s = fmaf(v, v, s);
        }
        #pragma unroll
        for (int o = 16; o; o >>= 1) s += __shfl_xor_sync(0xffffffffu, s, o);
        if (lane == 0) g_e2[row] = s;
        if (blockIdx.x == 0 && threadIdx.x == 0) { g_loss = 0.f; g_done = 0u; }
        return;
    }
    const int m0 = (blockIdx.x - 1024) * 32;
    const int t  = threadIdx.x;
    for (int i = t; i < 32 * Ff; i += 256) {
        int r = i / Ff, c = i - r * Ff;
        xs[r][c] = x[(m0 + r) * Ff + c];
    }
    __syncthreads();
    float acc0[32], acc1[32];
    const float b0 = b[t], b1 = b[t + 256];
    #pragma unroll
    for (int i = 0; i < 32; i++) { acc0[i] = b0; acc1[i] = b1; }
    float w0 = W[t], w1 = W[t + 256];
    for (int f = 0; f < Ff; f++) {
        float nw0 = 0.f, nw1 = 0.f;
        if (f + 1 < Ff) { nw0 = W[(f + 1) * Dm + t]; nw1 = W[(f + 1) * Dm + t + 256]; }
        #pragma unroll
        for (int i = 0; i < 32; i++) {
            float xv = xs[i][f];
            acc0[i] = fmaf(xv, w0, acc0[i]);
            acc1[i] = fmaf(xv, w1, acc1[i]);
        }
        w0 = nw0; w1 = nw1;
    }
    #pragma unroll
    for (int i = 0; i < 32; i++) {
        size_t zb = (size_t)(m0 + i) * Dm;
        g_z[zb + t] = acc0[i]; g_z[zb + t + 256] = acc1[i];
        size_t cbse = (size_t)(m0 + i) * KTOT;
        g_zc[cbse + t]       = __float2half_rn(acc0[i]);
        g_zc[cbse + t + 256] = __float2half_rn(acc1[i]);
    }
}

// ===== kernel 2: HMMA distance GEMM, 128-thr CTA, 2 CTAs/SM =====
__device__ __forceinline__ void load_stage(int gg, uint32_t sb, int t,
                                           int m0, int split) {
    const int ch = gg >> 3;
    const int st = gg & 7;
    const int d0 = st * KSTG;
    const int c0 = split * CODES_SPLIT + ch * NCHUNK;
    const uint32_t aB = sb, bB = sb + A_BYTES;
    #pragma unroll
    for (int i = 0; i < 8; i++) {
        int li = t + i * 128, row = li >> 3, c = li & 7;
        uint32_t sw = (uint32_t)(row * 128) + (uint32_t)(((c ^ (row & 7)) << 4));
        CP_ASYNC16(aB + sw, g_zc + (size_t)(m0 + row) * KTOT + d0 + c * 8);
    }
    #pragma unroll
    for (int i = 0; i < 8; i++) {
        int li = t + i * 128, row = li >> 3, c = li & 7;
        uint32_t sw = (uint32_t)(row * 128) + (uint32_t)(((c ^ (row & 7)) << 4));
        CP_ASYNC16(bB + sw, g_e16 + (size_t)(c0 + row) * Dm + d0 + c * 8);
    }
    CP_COMMIT();
}

__global__ __launch_bounds__(128, 2) void k_mma() {
    extern __shared__ __align__(16) char smem[];
    const uint32_t sb = smem_u32(smem);

    const int t = threadIdx.x;
    const int l = t & 31, wid = t >> 5;
    const int wm = wid & 1, wn = wid >> 1;       // 2 x 2 warp grid
    const int m0 = blockIdx.x * 128;
    const int split = blockIdx.y;
    const int l7 = l & 7, hi = (l >> 4) & 1, l15 = l & 15;

    uint32_t aBase[4], bBase[4];
    #pragma unroll
    for (int g4 = 0; g4 < 4; g4++) {
        aBase[g4] = (uint32_t)((wm * 64 + g4 * 16 + l15) * 128);
        bBase[g4] = (uint32_t)((wn * 64 + g4 * 16 + l15) * 128);
    }

    load_stage(0, sb + 0 * STAGE_BYTES, t, m0, split);
    load_stage(1, sb + 1 * STAGE_BYTES, t, m0, split);

    const float INF = __int_as_float(0x7f800000);
    float r1s[8], r2s[8]; int r1k[8], r2k[8];
    #pragma unroll
    for (int i = 0; i < 8; i++) { r1s[i] = INF; r2s[i] = INF; r1k[i] = 0x7fffffff; r2k[i] = 0x7fffffff; }

    int bufC = 0, bufP = 2;
    for (int ch = 0; ch < CHUNKS; ch++) {
        float acc[4][8][4];
        #pragma unroll
        for (int mt = 0; mt < 4; mt++)
            #pragma unroll
            for (int nt = 0; nt < 8; nt++)
                #pragma unroll
                for (int j = 0; j < 4; j++) acc[mt][nt][j] = 0.f;

        for (int st = 0; st < STG_CHUNK; st++) {
            const int g = ch * STG_CHUNK + st;
            if (g == G_TOT - 1) CP_WAIT0(); else CP_WAIT1();
            __syncthreads();
            if (g + 2 < G_TOT)
                load_stage(g + 2, sb + (uint32_t)bufP * STAGE_BYTES, t, m0, split);

            const uint32_t aO = sb + (uint32_t)bufC * STAGE_BYTES;
            const uint32_t bO = aO + A_BYTES;
            #pragma unroll
            for (int ks = 0; ks < 4; ks++) {
                const uint32_t xv = (uint32_t)((((ks * 2) + hi) ^ l7) << 4);
                uint32_t a[4][4], b[4][4];
                #pragma unroll
                for (int g4 = 0; g4 < 4; g4++)
                    LDSM4(a[g4][0], a[g4][1], a[g4][2], a[g4][3], aO + aBase[g4] + xv);
                #pragma unroll
                for (int g4 = 0; g4 < 4; g4++)
                    LDSM4(b[g4][0], b[g4][1], b[g4][2], b[g4][3], bO + bBase[g4] + xv);
                #pragma unroll
                for (int mt = 0; mt < 4; mt++)
                    #pragma unroll
                    for (int p = 0; p < 4; p++) {
                        MMA16816(acc[mt][2 * p],     a[mt][0], a[mt][1], a[mt][2], a[mt][3],
                                 b[p][0], b[p][2]);
                        MMA16816(acc[mt][2 * p + 1], a[mt][0], a[mt][1], a[mt][2], a[mt][3],
                                 b[p][1], b[p][3]);
                    }
            }
            bufC = (bufC == 2) ? 0 : bufC + 1;
            bufP = (bufP == 2) ? 0 : bufP + 1;
        }

        // chunk epilogue: score = e2 - 2*dot, fold into running top-2
        const int cb0 = split * CODES_SPLIT + ch * NCHUNK + wn * 64 + (l & 3) * 2;
        #pragma unroll
        for (int mt = 0; mt < 4; mt++) {
            #pragma unroll
            for (int h = 0; h < 2; h++) {
                const int ri = mt * 2 + h;
                #pragma unroll
                for (int nt = 0; nt < 8; nt++) {
                    int k0 = cb0 + nt * 8;
                    float e20 = g_e2[k0], e21 = g_e2[k0 + 1];
                    float s0 = fmaf(-2.f, acc[mt][nt][h * 2 + 0], e20);
                    float s1 = fmaf(-2.f, acc[mt][nt][h * 2 + 1], e21);
                    top2_upd(r1s[ri], r1k[ri], r2s[ri], r2k[ri], s0, k0);
                    top2_upd(r1s[ri], r1k[ri], r2s[ri], r2k[ri], s1, k0 + 1);
                }
            }
        }
    }

    // ---- final merge: 16 values per token row -> top-2 candidates ----
    __syncthreads();
    float* sS = (float*)smem;                 // [128][16] floats (8 KB)
    int*   sK = (int*)(smem + 128 * 16 * 4);  // [128][16] ints  (8 KB)
    const int slot = (wn * 4 + (l & 3)) * 2;
    #pragma unroll
    for (int mt = 0; mt < 4; mt++) {
        #pragma unroll
        for (int h = 0; h < 2; h++) {
            int ri = mt * 2 + h;
            int row = wm * 64 + mt * 16 + h * 8 + (l >> 2);
            sS[row * 16 + slot]     = r1s[ri];
            sS[row * 16 + slot + 1] = r2s[ri];
            sK[row * 16 + slot]     = r1k[ri];
            sK[row * 16 + slot + 1] = r2k[ri];
        }
    }
    __syncthreads();
    {
        float b1 = INF, b2 = INF; int i1 = 0x7fffffff, i2 = 0x7fffffff;
        #pragma unroll
        for (int j = 0; j < 16; j++) {
            float s = sS[t * 16 + j]; int k = sK[t * 16 + j];
            top2_upd(b1, i1, b2, i2, s, k);
        }
        g_cand[((size_t)split * M_TOK + m0 + t) * NCAND + 0] = i1;
        g_cand[((size_t)split * M_TOK + m0 + t) * NCAND + 1] = i2;
    }
}

// ===== kernel 3: exact recheck of 8, gather, out, loss (+final write) =====
__global__ __launch_bounds__(256) void k_out(const float* __restrict__ cb,
                                             const float* __restrict__ pos,
                                             float* __restrict__ out,
                                             int out_size) {
    const int m = blockIdx.x, t = threadIdx.x;
    const int w = t >> 5, lane = t & 31;
    __shared__ int scand[8];
    __shared__ float sdot[8];
    __shared__ int sBest;
    __shared__ float red[8];

    if (t < 8)
        scand[t] = g_cand[((size_t)(t >> 1) * M_TOK + m) * NCAND + (t & 1)];
    __syncthreads();

    const float* zr = g_z + (size_t)m * Dm;
    const int cidx = scand[w];
    const float* cr = cb + (size_t)cidx * Dm;
    float p = 0.f;
    #pragma unroll
    for (int i = 0; i < 16; i++) {
        int d = lane + i * 32;
        p = fmaf(zr[d], cr[d], p);
    }
    #pragma unroll
    for (int o = 16; o; o >>= 1) p += __shfl_xor_sync(0xffffffffu, p, o);
    if (lane == 0) sdot[w] = p;
    __syncthreads();

    if (t == 0) {
        float bsc = 3.4e38f; int bi = 0x7fffffff;
        #pragma unroll
        for (int q = 0; q < 8; q++) {
            int k = scand[q];
            float sc = fmaf(-2.f, sdot[q], g_e2[k]);
            if (sc < bsc || (sc == bsc && k < bi)) { bsc = sc; bi = k; }
        }
        sBest = bi;
    }
    __syncthreads();

    const int idx = sBest;
    const float* q  = cb  + (size_t)idx * Dm;
    const float* pr = pos + (m & (Cc - 1)) * Dm;
    float lsum = 0.f;
    #pragma unroll
    for (int r = 0; r < 2; r++) {
        int d = t + r * 256;
        float qv = q[d], zv = zr[d];
        out[(size_t)m * Dm + d] = qv + pr[d];
        float df = qv - zv;
        lsum = fmaf(df, df, lsum);
    }
    #pragma unroll
    for (int o = 16; o; o >>= 1) lsum += __shfl_xor_sync(0xffffffffu, lsum, o);
    if (lane == 0) red[w] = lsum;
    __syncthreads();
    if (t == 0) {
        float s = 0.f;
        #pragma unroll
        for (int ww = 0; ww < 8; ww++) s += red[ww];
        atomicAdd(&g_loss, s);
        __threadfence();
        unsigned prev = atomicAdd(&g_done, 1u);
        if (prev == (unsigned)(M_TOK - 1)) {
            // last block: all loss contributions visible; write scalar, reset
            float total = atomicAdd(&g_loss, 0.f);
            if (out_size > M_TOK * Dm)
                out[M_TOK * Dm] = total * (1.f / (float)((long)M_TOK * Dm));
            g_done = 0u;
        }
    }
}

// ===== launcher =====
extern "C" void kernel_launch(void* const* d_in, const int* in_sizes, int n_in,
                              void* d_out, int out_size) {
    const float* x   = (const float*)d_in[0];
    const float* W   = (const float*)d_in[1];
    const float* b   = (const float*)d_in[2];
    const float* cb  = (const float*)d_in[3];
    const float* pos = (const float*)d_in[4];
    float* out = (float*)d_out;

    cudaFuncSetAttribute(k_mma, cudaFuncAttributeMaxDynamicSharedMemorySize, SMEM_SZ);

    k_prep_z<<<1024 + M_TOK / 32, 256>>>(x, W, b, cb);
    k_mma   <<<dim3(M_TOK / 128, NSPLIT), 128, SMEM_SZ>>>();
    k_out   <<<M_TOK, 256>>>(cb, pos, out, out_size);
}

// round 14
// speedup vs baseline: 2.2809x; 1.0835x over previous
#include <cuda_runtime.h>
#include <cuda_fp16.h>
#include <cstdint>
#include <cstddef>

#define M_TOK 8192
#define Dm    512
#define Kcb   8192
#define Ff    129
#define Cc    64

// ---- MMA kernel geometry: 128-thread CTAs, 2 CTAs/SM ----
#define NSPLIT      4
#define CODES_SPLIT (Kcb / NSPLIT)      // 2048
#define NCHUNK      128                 // codes per chunk
#define CHUNKS      (CODES_SPLIT / NCHUNK) // 16
#define KTOT        512                 // fp16 z depth
#define KSTG        64                  // fp16 per stage
#define STG_CHUNK   (KTOT / KSTG)       // 8
#define G_TOT       (CHUNKS * STG_CHUNK)// 128
#define A_BYTES     16384               // 128 x 64 halfs
#define B_BYTES     16384               // 128 x 64 halfs
#define STAGE_BYTES (A_BYTES + B_BYTES) // 32768
#define SMEM_SZ     (3 * STAGE_BYTES)   // 98304 (2 CTAs/SM -> 192KB)
#define NCAND       2                   // top-2 per split, 4 splits -> 8 rechecked
#define XS_PITCH    36                  // padded token pitch (16B-aligned rows)

// ---- scratch ----
__device__ float  g_z[M_TOK * Dm];
__device__ __align__(16) __half g_zc[M_TOK * KTOT];
__device__ __align__(16) __half g_e16[Kcb * Dm];
__device__ float  g_e2[Kcb];
__device__ int    g_cand[NSPLIT * M_TOK * NCAND];
__device__ float  g_loss;
__device__ unsigned g_done;

// ---- PTX helpers (generic sm_80-class; valid under compute_103) ----
__device__ __forceinline__ uint32_t smem_u32(const void* p) {
    uint32_t r;
    asm("{ .reg .u64 t; cvta.to.shared.u64 t, %1; cvt.u32.u64 %0, t; }" : "=r"(r) : "l"(p));
    return r;
}
#define CP_ASYNC16(dst, src) \
    asm volatile("cp.async.cg.shared.global [%0], [%1], 16;" :: "r"(dst), "l"(src))
#define CP_COMMIT() asm volatile("cp.async.commit_group;" ::: "memory")
#define CP_WAIT0()  asm volatile("cp.async.wait_group 0;" ::: "memory")
#define CP_WAIT1()  asm volatile("cp.async.wait_group 1;" ::: "memory")

#define LDSM4(r0, r1, r2, r3, a) \
    asm volatile("ldmatrix.sync.aligned.m8n8.x4.shared.b16 {%0,%1,%2,%3}, [%4];" \
        : "=r"(r0), "=r"(r1), "=r"(r2), "=r"(r3) : "r"(a))

#define MMA16816(d, a0, a1, a2, a3, b0, b1) \
    asm volatile("mma.sync.aligned.m16n8k16.row.col.f32.f16.f16.f32 " \
        "{%0,%1,%2,%3}, {%4,%5,%6,%7}, {%8,%9}, {%0,%1,%2,%3};" \
        : "+f"((d)[0]), "+f"((d)[1]), "+f"((d)[2]), "+f"((d)[3]) \
        : "r"(a0), "r"(a1), "r"(a2), "r"(a3), "r"(b0), "r"(b1))

// hot-path top-2: no index tie-break (exact recheck re-applies reference
// tie-break on the candidate set; equal-score near-minima land in (s1,s2)).
__device__ __forceinline__ void top2_upd(float& s1, int& k1, float& s2, int& k2,
                                         float s, int k) {
    if (s < s1) { s2 = s1; k2 = k1; s1 = s; k1 = k; }
    else if (s < s2) { s2 = s; k2 = k; }
}

// ===== kernel 1 (fused): codebook prep (blocks 0..1023) + zgemm (1024..1279) =====
__global__ __launch_bounds__(256) void k_prep_z(const float* __restrict__ x,
                                                const float* __restrict__ W,
                                                const float* __restrict__ b,
                                                const float* __restrict__ cb) {
    __shared__ float xsT[Ff * XS_PITCH];   // transposed x tile: [f][token]
    if (blockIdx.x < 1024) {
        // ---- prep: e2 + fp16 codebook (vectorized) ----
        int row  = blockIdx.x * 8 + (threadIdx.x >> 5);
        int lane = threadIdx.x & 31;
        const float* r = cb + (size_t)row * Dm;
        float s = 0.f;
        #pragma unroll
        for (int i = lane * 4; i < Dm; i += 128) {
            float4 v = *(const float4*)&r[i];
            __half2 h01 = __floats2half2_rn(v.x, v.y);
            __half2 h23 = __floats2half2_rn(v.z, v.w);
            uint2 pk;
            pk.x = *(const uint32_t*)&h01;
            pk.y = *(const uint32_t*)&h23;
            *(uint2*)&g_e16[(size_t)row * Dm + i] = pk;
            s = fmaf(v.x, v.x, s); s = fmaf(v.y, v.y, s);
            s = fmaf(v.z, v.z, s); s = fmaf(v.w, v.w, s);
        }
        #pragma unroll
        for (int o = 16; o; o >>= 1) s += __shfl_xor_sync(0xffffffffu, s, o);
        if (lane == 0) g_e2[row] = s;
        if (blockIdx.x == 0 && threadIdx.x == 0) { g_loss = 0.f; g_done = 0u; }
        return;
    }
    // ---- zgemm: z = x @ W + b (fp32 + fp16 copies), transposed smem ----
    const int m0 = (blockIdx.x - 1024) * 32;
    const int t  = threadIdx.x;

    // fill xsT[f][token]: 8 threads per token, conflict-free banks
    {
        const int r = t >> 3;               // token 0..31
        for (int c = (t & 7); c < Ff; c += 8)
            xsT[c * XS_PITCH + r] = x[(m0 + r) * Ff + c];
    }
    __syncthreads();

    float acc0[32], acc1[32];
    const float b0 = b[t], b1 = b[t + 256];
    #pragma unroll
    for (int i = 0; i < 32; i++) { acc0[i] = b0; acc1[i] = b1; }

    float w0 = W[t], w1 = W[t + 256];
    for (int f = 0; f < Ff; f++) {
        float nw0 = 0.f, nw1 = 0.f;
        if (f + 1 < Ff) { nw0 = W[(f + 1) * Dm + t]; nw1 = W[(f + 1) * Dm + t + 256]; }
        const float4* xr = (const float4*)&xsT[f * XS_PITCH];
        #pragma unroll
        for (int i4 = 0; i4 < 8; i4++) {
            float4 xv = xr[i4];
            acc0[i4 * 4 + 0] = fmaf(xv.x, w0, acc0[i4 * 4 + 0]);
            acc1[i4 * 4 + 0] = fmaf(xv.x, w1, acc1[i4 * 4 + 0]);
            acc0[i4 * 4 + 1] = fmaf(xv.y, w0, acc0[i4 * 4 + 1]);
            acc1[i4 * 4 + 1] = fmaf(xv.y, w1, acc1[i4 * 4 + 1]);
            acc0[i4 * 4 + 2] = fmaf(xv.z, w0, acc0[i4 * 4 + 2]);
            acc1[i4 * 4 + 2] = fmaf(xv.z, w1, acc1[i4 * 4 + 2]);
            acc0[i4 * 4 + 3] = fmaf(xv.w, w0, acc0[i4 * 4 + 3]);
            acc1[i4 * 4 + 3] = fmaf(xv.w, w1, acc1[i4 * 4 + 3]);
        }
        w0 = nw0; w1 = nw1;
    }
    #pragma unroll
    for (int i = 0; i < 32; i++) {
        size_t zb = (size_t)(m0 + i) * Dm;
        g_z[zb + t] = acc0[i]; g_z[zb + t + 256] = acc1[i];
        size_t cbse = (size_t)(m0 + i) * KTOT;
        g_zc[cbse + t]       = __float2half_rn(acc0[i]);
        g_zc[cbse + t + 256] = __float2half_rn(acc1[i]);
    }
}

// ===== kernel 2: HMMA distance GEMM, 128-thr CTA, 2 CTAs/SM =====
__device__ __forceinline__ void load_stage(int gg, uint32_t sb, int t,
                                           int m0, int split) {
    const int ch = gg >> 3;
    const int st = gg & 7;
    const int d0 = st * KSTG;
    const int c0 = split * CODES_SPLIT + ch * NCHUNK;
    const uint32_t aB = sb, bB = sb + A_BYTES;
    #pragma unroll
    for (int i = 0; i < 8; i++) {
        int li = t + i * 128, row = li >> 3, c = li & 7;
        uint32_t sw = (uint32_t)(row * 128) + (uint32_t)(((c ^ (row & 7)) << 4));
        CP_ASYNC16(aB + sw, g_zc + (size_t)(m0 + row) * KTOT + d0 + c * 8);
    }
    #pragma unroll
    for (int i = 0; i < 8; i++) {
        int li = t + i * 128, row = li >> 3, c = li & 7;
        uint32_t sw = (uint32_t)(row * 128) + (uint32_t)(((c ^ (row & 7)) << 4));
        CP_ASYNC16(bB + sw, g_e16 + (size_t)(c0 + row) * Dm + d0 + c * 8);
    }
    CP_COMMIT();
}

__global__ __launch_bounds__(128, 2) void k_mma() {
    extern __shared__ __align__(16) char smem[];
    const uint32_t sb = smem_u32(smem);

    const int t = threadIdx.x;
    const int l = t & 31, wid = t >> 5;
    const int wm = wid & 1, wn = wid >> 1;       // 2 x 2 warp grid
    const int m0 = blockIdx.x * 128;
    const int split = blockIdx.y;
    const int l7 = l & 7, hi = (l >> 4) & 1, l15 = l & 15;

    uint32_t aBase[4], bBase[4];
    #pragma unroll
    for (int g4 = 0; g4 < 4; g4++) {
        aBase[g4] = (uint32_t)((wm * 64 + g4 * 16 + l15) * 128);
        bBase[g4] = (uint32_t)((wn * 64 + g4 * 16 + l15) * 128);
    }

    load_stage(0, sb + 0 * STAGE_BYTES, t, m0, split);
    load_stage(1, sb + 1 * STAGE_BYTES, t, m0, split);

    const float INF = __int_as_float(0x7f800000);
    float r1s[8], r2s[8]; int r1k[8], r2k[8];
    #pragma unroll
    for (int i = 0; i < 8; i++) { r1s[i] = INF; r2s[i] = INF; r1k[i] = 0x7fffffff; r2k[i] = 0x7fffffff; }

    int bufC = 0, bufP = 2;
    for (int ch = 0; ch < CHUNKS; ch++) {
        float acc[4][8][4];
        #pragma unroll
        for (int mt = 0; mt < 4; mt++)
            #pragma unroll
            for (int nt = 0; nt < 8; nt++)
                #pragma unroll
                for (int j = 0; j < 4; j++) acc[mt][nt][j] = 0.f;

        for (int st = 0; st < STG_CHUNK; st++) {
            const int g = ch * STG_CHUNK + st;
            if (g == G_TOT - 1) CP_WAIT0(); else CP_WAIT1();
            __syncthreads();
            if (g + 2 < G_TOT)
                load_stage(g + 2, sb + (uint32_t)bufP * STAGE_BYTES, t, m0, split);

            const uint32_t aO = sb + (uint32_t)bufC * STAGE_BYTES;
            const uint32_t bO = aO + A_BYTES;
            #pragma unroll
            for (int ks = 0; ks < 4; ks++) {
                const uint32_t xv = (uint32_t)((((ks * 2) + hi) ^ l7) << 4);
                uint32_t a[4][4], b[4][4];
                #pragma unroll
                for (int g4 = 0; g4 < 4; g4++)
                    LDSM4(a[g4][0], a[g4][1], a[g4][2], a[g4][3], aO + aBase[g4] + xv);
                #pragma unroll
                for (int g4 = 0; g4 < 4; g4++)
                    LDSM4(b[g4][0], b[g4][1], b[g4][2], b[g4][3], bO + bBase[g4] + xv);
                #pragma unroll
                for (int mt = 0; mt < 4; mt++)
                    #pragma unroll
                    for (int p = 0; p < 4; p++) {
                        MMA16816(acc[mt][2 * p],     a[mt][0], a[mt][1], a[mt][2], a[mt][3],
                                 b[p][0], b[p][2]);
                        MMA16816(acc[mt][2 * p + 1], a[mt][0], a[mt][1], a[mt][2], a[mt][3],
                                 b[p][1], b[p][3]);
                    }
            }
            bufC = (bufC == 2) ? 0 : bufC + 1;
            bufP = (bufP == 2) ? 0 : bufP + 1;
        }

        // chunk epilogue: score = e2 - 2*dot, fold into running top-2
        const int cb0 = split * CODES_SPLIT + ch * NCHUNK + wn * 64 + (l & 3) * 2;
        #pragma unroll
        for (int mt = 0; mt < 4; mt++) {
            #pragma unroll
            for (int h = 0; h < 2; h++) {
                const int ri = mt * 2 + h;
                #pragma unroll
                for (int nt = 0; nt < 8; nt++) {
                    int k0 = cb0 + nt * 8;
                    float e20 = g_e2[k0], e21 = g_e2[k0 + 1];
                    float s0 = fmaf(-2.f, acc[mt][nt][h * 2 + 0], e20);
                    float s1 = fmaf(-2.f, acc[mt][nt][h * 2 + 1], e21);
                    top2_upd(r1s[ri], r1k[ri], r2s[ri], r2k[ri], s0, k0);
                    top2_upd(r1s[ri], r1k[ri], r2s[ri], r2k[ri], s1, k0 + 1);
                }
            }
        }
    }

    // ---- final merge: 16 values per token row -> top-2 candidates ----
    __syncthreads();
    float* sS = (float*)smem;                 // [128][16] floats (8 KB)
    int*   sK = (int*)(smem + 128 * 16 * 4);  // [128][16] ints  (8 KB)
    const int slot = (wn * 4 + (l & 3)) * 2;
    #pragma unroll
    for (int mt = 0; mt < 4; mt++) {
        #pragma unroll
        for (int h = 0; h < 2; h++) {
            int ri = mt * 2 + h;
            int row = wm * 64 + mt * 16 + h * 8 + (l >> 2);
            sS[row * 16 + slot]     = r1s[ri];
            sS[row * 16 + slot + 1] = r2s[ri];
            sK[row * 16 + slot]     = r1k[ri];
            sK[row * 16 + slot + 1] = r2k[ri];
        }
    }
    __syncthreads();
    {
        float b1 = INF, b2 = INF; int i1 = 0x7fffffff, i2 = 0x7fffffff;
        #pragma unroll
        for (int j = 0; j < 16; j++) {
            float s = sS[t * 16 + j]; int k = sK[t * 16 + j];
            top2_upd(b1, i1, b2, i2, s, k);
        }
        g_cand[((size_t)split * M_TOK + m0 + t) * NCAND + 0] = i1;
        g_cand[((size_t)split * M_TOK + m0 + t) * NCAND + 1] = i2;
    }
}

// ===== kernel 3: exact recheck of 8, gather, out, loss (+final write) =====
__global__ __launch_bounds__(256) void k_out(const float* __restrict__ cb,
                                             const float* __restrict__ pos,
                                             float* __restrict__ out,
                                             int out_size) {
    const int m = blockIdx.x, t = threadIdx.x;
    const int w = t >> 5, lane = t & 31;
    __shared__ int scand[8];
    __shared__ float sdot[8];
    __shared__ int sBest;
    __shared__ float red[8];

    if (t < 8)
        scand[t] = g_cand[((size_t)(t >> 1) * M_TOK + m) * NCAND + (t & 1)];
    __syncthreads();

    const float* zr = g_z + (size_t)m * Dm;
    const int cidx = scand[w];
    const float* cr = cb + (size_t)cidx * Dm;
    float p = 0.f;
    #pragma unroll
    for (int i = 0; i < 16; i++) {
        int d = lane + i * 32;
        p = fmaf(zr[d], cr[d], p);
    }
    #pragma unroll
    for (int o = 16; o; o >>= 1) p += __shfl_xor_sync(0xffffffffu, p, o);
    if (lane == 0) sdot[w] = p;
    __syncthreads();

    if (t == 0) {
        float bsc = 3.4e38f; int bi = 0x7fffffff;
        #pragma unroll
        for (int q = 0; q < 8; q++) {
            int k = scand[q];
            float sc = fmaf(-2.f, sdot[q], g_e2[k]);
            if (sc < bsc || (sc == bsc && k < bi)) { bsc = sc; bi = k; }
        }
        sBest = bi;
    }
    __syncthreads();

    const int idx = sBest;
    const float* q  = cb  + (size_t)idx * Dm;
    const float* pr = pos + (m & (Cc - 1)) * Dm;
    float lsum = 0.f;
    #pragma unroll
    for (int r = 0; r < 2; r++) {
        int d = t + r * 256;
        float qv = q[d], zv = zr[d];
        out[(size_t)m * Dm + d] = qv + pr[d];
        float df = qv - zv;
        lsum = fmaf(df, df, lsum);
    }
    #pragma unroll
    for (int o = 16; o; o >>= 1) lsum += __shfl_xor_sync(0xffffffffu, lsum, o);
    if (lane == 0) red[w] = lsum;
    __syncthreads();
    if (t == 0) {
        float s = 0.f;
        #pragma unroll
        for (int ww = 0; ww < 8; ww++) s += red[ww];
        atomicAdd(&g_loss, s);
        __threadfence();
        unsigned prev = atomicAdd(&g_done, 1u);
        if (prev == (unsigned)(M_TOK - 1)) {
            float total = atomicAdd(&g_loss, 0.f);
            if (out_size > M_TOK * Dm)
                out[M_TOK * Dm] = total * (1.f / (float)((long)M_TOK * Dm));
            g_done = 0u;
        }
    }
}

// ===== launcher =====
extern "C" void kernel_launch(void* const* d_in, const int* in_sizes, int n_in,
                              void* d_out, int out_size) {
    const float* x   = (const float*)d_in[0];
    const float* W   = (const float*)d_in[1];
    const float* b   = (const float*)d_in[2];
    const float* cb  = (const float*)d_in[3];
    const float* pos = (const float*)d_in[4];
    float* out = (float*)d_out;

    cudaFuncSetAttribute(k_mma, cudaFuncAttributeMaxDynamicSharedMemorySize, SMEM_SZ);

    k_prep_z<<<1024 + M_TOK / 32, 256>>>(x, W, b, cb);
    k_mma   <<<dim3(M_TOK / 128, NSPLIT), 128, SMEM_SZ>>>();
    k_out   <<<M_TOK, 256>>>(cb, pos, out, out_size);
}

// round 15
// speedup vs baseline: 2.3019x; 1.0092x over previous
#include <cuda_runtime.h>
#include <cuda_fp16.h>
#include <cstdint>
#include <cstddef>

#define M_TOK 8192
#define Dm    512
#define Kcb   8192
#define Ff    129
#define Cc    64

// ---- MMA kernel geometry: 128-thread CTAs, 2 CTAs/SM ----
#define NSPLIT      4
#define CODES_SPLIT (Kcb / NSPLIT)      // 2048
#define NCHUNK      128                 // codes per chunk
#define CHUNKS      (CODES_SPLIT / NCHUNK) // 16
#define KTOT        512                 // fp16 z depth
#define KSTG        64                  // fp16 per stage
#define STG_CHUNK   (KTOT / KSTG)       // 8
#define G_TOT       (CHUNKS * STG_CHUNK)// 128
#define A_BYTES     16384               // 128 x 64 halfs
#define B_BYTES     16384               // 128 x 64 halfs
#define STAGE_BYTES (A_BYTES + B_BYTES) // 32768
#define SMEM_SZ     (3 * STAGE_BYTES)   // 98304 (2 CTAs/SM -> 192KB)
#define NCAND       2                   // top-2 per split, 4 splits -> 8 rechecked
#define XS_PITCH    36                  // padded token pitch (16B-aligned rows)

// ---- scratch ----
__device__ float  g_z[M_TOK * Dm];
__device__ __align__(16) __half g_zc[M_TOK * KTOT];
__device__ __align__(16) __half g_e16[Kcb * Dm];
__device__ float  g_e2[Kcb];
__device__ int    g_cand[NSPLIT * M_TOK * NCAND];
__device__ float  g_loss;
__device__ unsigned g_done;

// ---- PTX helpers (generic sm_80-class; valid under compute_103) ----
__device__ __forceinline__ uint32_t smem_u32(const void* p) {
    uint32_t r;
    asm("{ .reg .u64 t; cvta.to.shared.u64 t, %1; cvt.u32.u64 %0, t; }" : "=r"(r) : "l"(p));
    return r;
}
#define CP_ASYNC16(dst, src) \
    asm volatile("cp.async.cg.shared.global [%0], [%1], 16;" :: "r"(dst), "l"(src))
#define CP_COMMIT() asm volatile("cp.async.commit_group;" ::: "memory")
#define CP_WAIT0()  asm volatile("cp.async.wait_group 0;" ::: "memory")
#define CP_WAIT1()  asm volatile("cp.async.wait_group 1;" ::: "memory")

#define LDSM4(r0, r1, r2, r3, a) \
    asm volatile("ldmatrix.sync.aligned.m8n8.x4.shared.b16 {%0,%1,%2,%3}, [%4];" \
        : "=r"(r0), "=r"(r1), "=r"(r2), "=r"(r3) : "r"(a))

#define MMA16816(d, a0, a1, a2, a3, b0, b1) \
    asm volatile("mma.sync.aligned.m16n8k16.row.col.f32.f16.f16.f32 " \
        "{%0,%1,%2,%3}, {%4,%5,%6,%7}, {%8,%9}, {%0,%1,%2,%3};" \
        : "+f"((d)[0]), "+f"((d)[1]), "+f"((d)[2]), "+f"((d)[3]) \
        : "r"(a0), "r"(a1), "r"(a2), "r"(a3), "r"(b0), "r"(b1))

// hot-path top-2: no index tie-break (exact recheck re-applies reference
// tie-break on the candidate set; equal-score near-minima land in (s1,s2)).
__device__ __forceinline__ void top2_upd(float& s1, int& k1, float& s2, int& k2,
                                         float s, int k) {
    if (s < s1) { s2 = s1; k2 = k1; s1 = s; k1 = k; }
    else if (s < s2) { s2 = s; k2 = k; }
}

// ===== kernel 1 (fused): codebook prep (blocks 0..1023) + zgemm (1024..1279) =====
__global__ __launch_bounds__(256) void k_prep_z(const float* __restrict__ x,
                                                const float* __restrict__ W,
                                                const float* __restrict__ b,
                                                const float* __restrict__ cb) {
    __shared__ float xsT[Ff * XS_PITCH];   // transposed x tile: [f][token]
    if (blockIdx.x < 1024) {
        // ---- prep: e2 + fp16 codebook (vectorized) ----
        int row  = blockIdx.x * 8 + (threadIdx.x >> 5);
        int lane = threadIdx.x & 31;
        const float* r = cb + (size_t)row * Dm;
        float s = 0.f;
        #pragma unroll
        for (int i = lane * 4; i < Dm; i += 128) {
            float4 v = *(const float4*)&r[i];
            __half2 h01 = __floats2half2_rn(v.x, v.y);
            __half2 h23 = __floats2half2_rn(v.z, v.w);
            uint2 pk;
            pk.x = *(const uint32_t*)&h01;
            pk.y = *(const uint32_t*)&h23;
            *(uint2*)&g_e16[(size_t)row * Dm + i] = pk;
            s = fmaf(v.x, v.x, s); s = fmaf(v.y, v.y, s);
            s = fmaf(v.z, v.z, s); s = fmaf(v.w, v.w, s);
        }
        #pragma unroll
        for (int o = 16; o; o >>= 1) s += __shfl_xor_sync(0xffffffffu, s, o);
        if (lane == 0) g_e2[row] = s;
        if (blockIdx.x == 0 && threadIdx.x == 0) { g_loss = 0.f; g_done = 0u; }
        return;
    }
    // ---- zgemm: z = x @ W + b, transposed smem x + 4-deep W ring ----
    const int m0 = (blockIdx.x - 1024) * 32;
    const int t  = threadIdx.x;

    {
        const int r = t >> 3;               // token 0..31
        for (int c = (t & 7); c < Ff; c += 8)
            xsT[c * XS_PITCH + r] = x[(m0 + r) * Ff + c];
    }
    __syncthreads();

    float acc0[32], acc1[32];
    const float b0 = b[t], b1 = b[t + 256];
    #pragma unroll
    for (int i = 0; i < 32; i++) { acc0[i] = b0; acc1[i] = b1; }

    float w0[4], w1[4];
    #pragma unroll
    for (int j = 0; j < 4; j++) {
        w0[j] = W[j * Dm + t];
        w1[j] = W[j * Dm + t + 256];
    }

    for (int f0 = 0; f0 < Ff - 1; f0 += 4) {      // 0..124 step 4 (f=0..127)
        #pragma unroll
        for (int j = 0; j < 4; j++) {
            const int f = f0 + j;
            const float cw0 = w0[j], cw1 = w1[j];
            const int fn = f + 4;
            if (fn < Ff) {                        // prefetch 4 ahead
                w0[j] = W[fn * Dm + t];
                w1[j] = W[fn * Dm + t + 256];
            }
            const float4* xr = (const float4*)&xsT[f * XS_PITCH];
            #pragma unroll
            for (int i4 = 0; i4 < 8; i4++) {
                float4 xv = xr[i4];
                acc0[i4 * 4 + 0] = fmaf(xv.x, cw0, acc0[i4 * 4 + 0]);
                acc1[i4 * 4 + 0] = fmaf(xv.x, cw1, acc1[i4 * 4 + 0]);
                acc0[i4 * 4 + 1] = fmaf(xv.y, cw0, acc0[i4 * 4 + 1]);
                acc1[i4 * 4 + 1] = fmaf(xv.y, cw1, acc1[i4 * 4 + 1]);
                acc0[i4 * 4 + 2] = fmaf(xv.z, cw0, acc0[i4 * 4 + 2]);
                acc1[i4 * 4 + 2] = fmaf(xv.z, cw1, acc1[i4 * 4 + 2]);
                acc0[i4 * 4 + 3] = fmaf(xv.w, cw0, acc0[i4 * 4 + 3]);
                acc1[i4 * 4 + 3] = fmaf(xv.w, cw1, acc1[i4 * 4 + 3]);
            }
        }
    }
    {   // tail f = 128 (prefetched into ring slot 0)
        const float cw0 = w0[0], cw1 = w1[0];
        const float4* xr = (const float4*)&xsT[(Ff - 1) * XS_PITCH];
        #pragma unroll
        for (int i4 = 0; i4 < 8; i4++) {
            float4 xv = xr[i4];
            acc0[i4 * 4 + 0] = fmaf(xv.x, cw0, acc0[i4 * 4 + 0]);
            acc1[i4 * 4 + 0] = fmaf(xv.x, cw1, acc1[i4 * 4 + 0]);
            acc0[i4 * 4 + 1] = fmaf(xv.y, cw0, acc0[i4 * 4 + 1]);
            acc1[i4 * 4 + 1] = fmaf(xv.y, cw1, acc1[i4 * 4 + 1]);
            acc0[i4 * 4 + 2] = fmaf(xv.z, cw0, acc0[i4 * 4 + 2]);
            acc1[i4 * 4 + 2] = fmaf(xv.z, cw1, acc1[i4 * 4 + 2]);
            acc0[i4 * 4 + 3] = fmaf(xv.w, cw0, acc0[i4 * 4 + 3]);
            acc1[i4 * 4 + 3] = fmaf(xv.w, cw1, acc1[i4 * 4 + 3]);
        }
    }
    #pragma unroll
    for (int i = 0; i < 32; i++) {
        size_t zb = (size_t)(m0 + i) * Dm;
        g_z[zb + t] = acc0[i]; g_z[zb + t + 256] = acc1[i];
        size_t cbse = (size_t)(m0 + i) * KTOT;
        g_zc[cbse + t]       = __float2half_rn(acc0[i]);
        g_zc[cbse + t + 256] = __float2half_rn(acc1[i]);
    }
}

// ===== kernel 2: HMMA distance GEMM, 128-thr CTA, 2 CTAs/SM =====
__device__ __forceinline__ void load_stage(int gg, uint32_t sb, int t,
                                           int m0, int split) {
    const int ch = gg >> 3;
    const int st = gg & 7;
    const int d0 = st * KSTG;
    const int c0 = split * CODES_SPLIT + ch * NCHUNK;
    const uint32_t aB = sb, bB = sb + A_BYTES;
    #pragma unroll
    for (int i = 0; i < 8; i++) {
        int li = t + i * 128, row = li >> 3, c = li & 7;
        uint32_t sw = (uint32_t)(row * 128) + (uint32_t)(((c ^ (row & 7)) << 4));
        CP_ASYNC16(aB + sw, g_zc + (size_t)(m0 + row) * KTOT + d0 + c * 8);
    }
    #pragma unroll
    for (int i = 0; i < 8; i++) {
        int li = t + i * 128, row = li >> 3, c = li & 7;
        uint32_t sw = (uint32_t)(row * 128) + (uint32_t)(((c ^ (row & 7)) << 4));
        CP_ASYNC16(bB + sw, g_e16 + (size_t)(c0 + row) * Dm + d0 + c * 8);
    }
    CP_COMMIT();
}

__global__ __launch_bounds__(128, 2) void k_mma() {
    extern __shared__ __align__(16) char smem[];
    const uint32_t sb = smem_u32(smem);

    const int t = threadIdx.x;
    const int l = t & 31, wid = t >> 5;
    const int wm = wid & 1, wn = wid >> 1;       // 2 x 2 warp grid
    const int m0 = blockIdx.x * 128;
    const int split = blockIdx.y;
    const int l7 = l & 7, hi = (l >> 4) & 1, l15 = l & 15;

    uint32_t aBase[4], bBase[4];
    #pragma unroll
    for (int g4 = 0; g4 < 4; g4++) {
        aBase[g4] = (uint32_t)((wm * 64 + g4 * 16 + l15) * 128);
        bBase[g4] = (uint32_t)((wn * 64 + g4 * 16 + l15) * 128);
    }

    load_stage(0, sb + 0 * STAGE_BYTES, t, m0, split);
    load_stage(1, sb + 1 * STAGE_BYTES, t, m0, split);

    const float INF = __int_as_float(0x7f800000);
    float r1s[8], r2s[8]; int r1k[8], r2k[8];
    #pragma unroll
    for (int i = 0; i < 8; i++) { r1s[i] = INF; r2s[i] = INF; r1k[i] = 0x7fffffff; r2k[i] = 0x7fffffff; }

    int bufC = 0, bufP = 2;
    for (int ch = 0; ch < CHUNKS; ch++) {
        float acc[4][8][4];
        #pragma unroll
        for (int mt = 0; mt < 4; mt++)
            #pragma unroll
            for (int nt = 0; nt < 8; nt++)
                #pragma unroll
                for (int j = 0; j < 4; j++) acc[mt][nt][j] = 0.f;

        for (int st = 0; st < STG_CHUNK; st++) {
            const int g = ch * STG_CHUNK + st;
            if (g == G_TOT - 1) CP_WAIT0(); else CP_WAIT1();
            __syncthreads();
            if (g + 2 < G_TOT)
                load_stage(g + 2, sb + (uint32_t)bufP * STAGE_BYTES, t, m0, split);

            const uint32_t aO = sb + (uint32_t)bufC * STAGE_BYTES;
            const uint32_t bO = aO + A_BYTES;
            #pragma unroll
            for (int ks = 0; ks < 4; ks++) {
                const uint32_t xv = (uint32_t)((((ks * 2) + hi) ^ l7) << 4);
                uint32_t a[4][4], b[4][4];
                #pragma unroll
                for (int g4 = 0; g4 < 4; g4++)
                    LDSM4(a[g4][0], a[g4][1], a[g4][2], a[g4][3], aO + aBase[g4] + xv);
                #pragma unroll
                for (int g4 = 0; g4 < 4; g4++)
                    LDSM4(b[g4][0], b[g4][1], b[g4][2], b[g4][3], bO + bBase[g4] + xv);
                #pragma unroll
                for (int mt = 0; mt < 4; mt++)
                    #pragma unroll
                    for (int p = 0; p < 4; p++) {
                        MMA16816(acc[mt][2 * p],     a[mt][0], a[mt][1], a[mt][2], a[mt][3],
                                 b[p][0], b[p][2]);
                        MMA16816(acc[mt][2 * p + 1], a[mt][0], a[mt][1], a[mt][2], a[mt][3],
                                 b[p][1], b[p][3]);
                    }
            }
            bufC = (bufC == 2) ? 0 : bufC + 1;
            bufP = (bufP == 2) ? 0 : bufP + 1;
        }

        // chunk epilogue: score = e2 - 2*dot, fold into running top-2
        const int cb0 = split * CODES_SPLIT + ch * NCHUNK + wn * 64 + (l & 3) * 2;
        #pragma unroll
        for (int mt = 0; mt < 4; mt++) {
            #pragma unroll
            for (int h = 0; h < 2; h++) {
                const int ri = mt * 2 + h;
                #pragma unroll
                for (int nt = 0; nt < 8; nt++) {
                    int k0 = cb0 + nt * 8;
                    float e20 = g_e2[k0], e21 = g_e2[k0 + 1];
                    float s0 = fmaf(-2.f, acc[mt][nt][h * 2 + 0], e20);
                    float s1 = fmaf(-2.f, acc[mt][nt][h * 2 + 1], e21);
                    top2_upd(r1s[ri], r1k[ri], r2s[ri], r2k[ri], s0, k0);
                    top2_upd(r1s[ri], r1k[ri], r2s[ri], r2k[ri], s1, k0 + 1);
                }
            }
        }
    }

    // ---- final merge: 16 values per token row -> top-2 candidates ----
    __syncthreads();
    float* sS = (float*)smem;                 // [128][16] floats (8 KB)
    int*   sK = (int*)(smem + 128 * 16 * 4);  // [128][16] ints  (8 KB)
    const int slot = (wn * 4 + (l & 3)) * 2;
    #pragma unroll
    for (int mt = 0; mt < 4; mt++) {
        #pragma unroll
        for (int h = 0; h < 2; h++) {
            int ri = mt * 2 + h;
            int row = wm * 64 + mt * 16 + h * 8 + (l >> 2);
            sS[row * 16 + slot]     = r1s[ri];
            sS[row * 16 + slot + 1] = r2s[ri];
            sK[row * 16 + slot]     = r1k[ri];
            sK[row * 16 + slot + 1] = r2k[ri];
        }
    }
    __syncthreads();
    {
        float b1 = INF, b2 = INF; int i1 = 0x7fffffff, i2 = 0x7fffffff;
        #pragma unroll
        for (int j = 0; j < 16; j++) {
            float s = sS[t * 16 + j]; int k = sK[t * 16 + j];
            top2_upd(b1, i1, b2, i2, s, k);
        }
        g_cand[((size_t)split * M_TOK + m0 + t) * NCAND + 0] = i1;
        g_cand[((size_t)split * M_TOK + m0 + t) * NCAND + 1] = i2;
    }
}

// ===== kernel 3: exact recheck of 8, gather, out, loss (+final write) =====
__global__ __launch_bounds__(256) void k_out(const float* __restrict__ cb,
                                             const float* __restrict__ pos,
                                             float* __restrict__ out,
                                             int out_size) {
    const int m = blockIdx.x, t = threadIdx.x;
    const int w = t >> 5, lane = t & 31;
    __shared__ int scand[8];
    __shared__ float sdot[8];
    __shared__ int sBest;
    __shared__ float red[8];

    if (t < 8)
        scand[t] = g_cand[((size_t)(t >> 1) * M_TOK + m) * NCAND + (t & 1)];
    __syncthreads();

    const float* zr = g_z + (size_t)m * Dm;
    const int cidx = scand[w];
    const float* cr = cb + (size_t)cidx * Dm;
    float p = 0.f;
    #pragma unroll
    for (int i = 0; i < 4; i++) {
        int d = lane * 4 + i * 128;
        float4 zv = *(const float4*)&zr[d];
        float4 cv = *(const float4*)&cr[d];
        p = fmaf(zv.x, cv.x, p);
        p = fmaf(zv.y, cv.y, p);
        p = fmaf(zv.z, cv.z, p);
        p = fmaf(zv.w, cv.w, p);
    }
    #pragma unroll
    for (int o = 16; o; o >>= 1) p += __shfl_xor_sync(0xffffffffu, p, o);
    if (lane == 0) sdot[w] = p;
    __syncthreads();

    if (t == 0) {
        float bsc = 3.4e38f; int bi = 0x7fffffff;
        #pragma unroll
        for (int q = 0; q < 8; q++) {
            int k = scand[q];
            float sc = fmaf(-2.f, sdot[q], g_e2[k]);
            if (sc < bsc || (sc == bsc && k < bi)) { bsc = sc; bi = k; }
        }
        sBest = bi;
    }
    __syncthreads();

    const int idx = sBest;
    const float* q  = cb  + (size_t)idx * Dm;
    const float* pr = pos + (m & (Cc - 1)) * Dm;
    float lsum = 0.f;
    #pragma unroll
    for (int r = 0; r < 2; r++) {
        int d = t + r * 256;
        float qv = q[d], zv = zr[d];
        out[(size_t)m * Dm + d] = qv + pr[d];
        float df = qv - zv;
        lsum = fmaf(df, df, lsum);
    }
    #pragma unroll
    for (int o = 16; o; o >>= 1) lsum += __shfl_xor_sync(0xffffffffu, lsum, o);
    if (lane == 0) red[w] = lsum;
    __syncthreads();
    if (t == 0) {
        float s = 0.f;
        #pragma unroll
        for (int ww = 0; ww < 8; ww++) s += red[ww];
        atomicAdd(&g_loss, s);
        __threadfence();
        unsigned prev = atomicAdd(&g_done, 1u);
        if (prev == (unsigned)(M_TOK - 1)) {
            float total = atomicAdd(&g_loss, 0.f);
            if (out_size > M_TOK * Dm)
                out[M_TOK * Dm] = total * (1.f / (float)((long)M_TOK * Dm));
            g_done = 0u;
        }
    }
}

// ===== launcher =====
extern "C" void kernel_launch(void* const* d_in, const int* in_sizes, int n_in,
                              void* d_out, int out_size) {
    const float* x   = (const float*)d_in[0];
    const float* W   = (const float*)d_in[1];
    const float* b   = (const float*)d_in[2];
    const float* cb  = (const float*)d_in[3];
    const float* pos = (const float*)d_in[4];
    float* out = (float*)d_out;

    cudaFuncSetAttribute(k_mma, cudaFuncAttributeMaxDynamicSharedMemorySize, SMEM_SZ);

    k_prep_z<<<1024 + M_TOK / 32, 256>>>(x, W, b, cb);
    k_mma   <<<dim3(M_TOK / 128, NSPLIT), 128, SMEM_SZ>>>();
    k_out   <<<M_TOK, 256>>>(cb, pos, out, out_size);
}

// round 16
// speedup vs baseline: 2.3674x; 1.0284x over previous
#include <cuda_runtime.h>
#include <cuda_fp16.h>
#include <cstdint>
#include <cstddef>

#define M_TOK 8192
#define Dm    512
#define Kcb   8192
#define Ff    129
#define Cc    64

// ---- MMA kernel geometry: 128-thread CTAs, 2 CTAs/SM ----
#define NSPLIT      4
#define CODES_SPLIT (Kcb / NSPLIT)      // 2048
#define NCHUNK      128                 // codes per chunk
#define CHUNKS      (CODES_SPLIT / NCHUNK) // 16
#define KTOT        512                 // fp16 z depth
#define KSTG        64                  // fp16 per stage
#define STG_CHUNK   (KTOT / KSTG)       // 8
#define G_TOT       (CHUNKS * STG_CHUNK)// 128
#define A_BYTES     16384               // 128 x 64 halfs
#define B_BYTES     16384               // 128 x 64 halfs
#define STAGE_BYTES (A_BYTES + B_BYTES) // 32768
#define SMEM_SZ     (3 * STAGE_BYTES)   // 98304 (2 CTAs/SM -> 192KB)
#define NCAND       2                   // top-2 per split, 4 splits -> 8 rechecked
#define XS_PITCH    36                  // padded token pitch (16B-aligned rows)

// ---- scratch ----
__device__ float  g_z[M_TOK * Dm];
__device__ __align__(16) __half g_zc[M_TOK * KTOT];
__device__ __align__(16) __half g_e16[Kcb * Dm];
__device__ float  g_e2[Kcb];
__device__ int    g_cand[NSPLIT * M_TOK * NCAND];
__device__ float  g_loss;
__device__ unsigned g_done;

// ---- PTX helpers (generic sm_80-class; valid under compute_103) ----
__device__ __forceinline__ uint32_t smem_u32(const void* p) {
    uint32_t r;
    asm("{ .reg .u64 t; cvta.to.shared.u64 t, %1; cvt.u32.u64 %0, t; }" : "=r"(r) : "l"(p));
    return r;
}
#define CP_ASYNC16(dst, src) \
    asm volatile("cp.async.cg.shared.global [%0], [%1], 16;" :: "r"(dst), "l"(src))
#define CP_COMMIT() asm volatile("cp.async.commit_group;" ::: "memory")
#define CP_WAIT0()  asm volatile("cp.async.wait_group 0;" ::: "memory")
#define CP_WAIT1()  asm volatile("cp.async.wait_group 1;" ::: "memory")

#define LDSM4(r0, r1, r2, r3, a) \
    asm volatile("ldmatrix.sync.aligned.m8n8.x4.shared.b16 {%0,%1,%2,%3}, [%4];" \
        : "=r"(r0), "=r"(r1), "=r"(r2), "=r"(r3) : "r"(a))

// fp16-accumulator MMA: D(f16x2 regs)[16x8] += A[16x16] * B[8x16]
#define MMA16816H(d, a0, a1, a2, a3, b0, b1) \
    asm volatile("mma.sync.aligned.m16n8k16.row.col.f16.f16.f16.f16 " \
        "{%0,%1}, {%2,%3,%4,%5}, {%6,%7}, {%0,%1};" \
        : "+r"((d)[0]), "+r"((d)[1]) \
        : "r"(a0), "r"(a1), "r"(a2), "r"(a3), "r"(b0), "r"(b1))

// hot-path top-2: no index tie-break (exact recheck re-applies reference
// tie-break on the candidate set; equal-score near-minima land in (s1,s2)).
__device__ __forceinline__ void top2_upd(float& s1, int& k1, float& s2, int& k2,
                                         float s, int k) {
    if (s < s1) { s2 = s1; k2 = k1; s1 = s; k1 = k; }
    else if (s < s2) { s2 = s; k2 = k; }
}

// ===== kernel 1 (fused): codebook prep (blocks 0..1023) + zgemm (1024..1279) =====
__global__ __launch_bounds__(256) void k_prep_z(const float* __restrict__ x,
                                                const float* __restrict__ W,
                                                const float* __restrict__ b,
                                                const float* __restrict__ cb) {
    __shared__ float xsT[Ff * XS_PITCH];   // transposed x tile: [f][token]
    if (blockIdx.x < 1024) {
        // ---- prep: e2 + fp16 codebook (vectorized) ----
        int row  = blockIdx.x * 8 + (threadIdx.x >> 5);
        int lane = threadIdx.x & 31;
        const float* r = cb + (size_t)row * Dm;
        float s = 0.f;
        #pragma unroll
        for (int i = lane * 4; i < Dm; i += 128) {
            float4 v = *(const float4*)&r[i];
            __half2 h01 = __floats2half2_rn(v.x, v.y);
            __half2 h23 = __floats2half2_rn(v.z, v.w);
            uint2 pk;
            pk.x = *(const uint32_t*)&h01;
            pk.y = *(const uint32_t*)&h23;
            *(uint2*)&g_e16[(size_t)row * Dm + i] = pk;
            s = fmaf(v.x, v.x, s); s = fmaf(v.y, v.y, s);
            s = fmaf(v.z, v.z, s); s = fmaf(v.w, v.w, s);
        }
        #pragma unroll
        for (int o = 16; o; o >>= 1) s += __shfl_xor_sync(0xffffffffu, s, o);
        if (lane == 0) g_e2[row] = s;
        if (blockIdx.x == 0 && threadIdx.x == 0) { g_loss = 0.f; g_done = 0u; }
        return;
    }
    // ---- zgemm: z = x @ W + b, transposed smem x + 4-deep W ring ----
    const int m0 = (blockIdx.x - 1024) * 32;
    const int t  = threadIdx.x;

    {
        const int r = t >> 3;               // token 0..31
        for (int c = (t & 7); c < Ff; c += 8)
            xsT[c * XS_PITCH + r] = x[(m0 + r) * Ff + c];
    }
    __syncthreads();

    float acc0[32], acc1[32];
    const float b0 = b[t], b1 = b[t + 256];
    #pragma unroll
    for (int i = 0; i < 32; i++) { acc0[i] = b0; acc1[i] = b1; }

    float w0[4], w1[4];
    #pragma unroll
    for (int j = 0; j < 4; j++) {
        w0[j] = W[j * Dm + t];
        w1[j] = W[j * Dm + t + 256];
    }

    for (int f0 = 0; f0 < Ff - 1; f0 += 4) {      // 0..124 step 4 (f=0..127)
        #pragma unroll
        for (int j = 0; j < 4; j++) {
            const int f = f0 + j;
            const float cw0 = w0[j], cw1 = w1[j];
            const int fn = f + 4;
            if (fn < Ff) {                        // prefetch 4 ahead
                w0[j] = W[fn * Dm + t];
                w1[j] = W[fn * Dm + t + 256];
            }
            const float4* xr = (const float4*)&xsT[f * XS_PITCH];
            #pragma unroll
            for (int i4 = 0; i4 < 8; i4++) {
                float4 xv = xr[i4];
                acc0[i4 * 4 + 0] = fmaf(xv.x, cw0, acc0[i4 * 4 + 0]);
                acc1[i4 * 4 + 0] = fmaf(xv.x, cw1, acc1[i4 * 4 + 0]);
                acc0[i4 * 4 + 1] = fmaf(xv.y, cw0, acc0[i4 * 4 + 1]);
                acc1[i4 * 4 + 1] = fmaf(xv.y, cw1, acc1[i4 * 4 + 1]);
                acc0[i4 * 4 + 2] = fmaf(xv.z, cw0, acc0[i4 * 4 + 2]);
                acc1[i4 * 4 + 2] = fmaf(xv.z, cw1, acc1[i4 * 4 + 2]);
                acc0[i4 * 4 + 3] = fmaf(xv.w, cw0, acc0[i4 * 4 + 3]);
                acc1[i4 * 4 + 3] = fmaf(xv.w, cw1, acc1[i4 * 4 + 3]);
            }
        }
    }
    {   // tail f = 128 (prefetched into ring slot 0)
        const float cw0 = w0[0], cw1 = w1[0];
        const float4* xr = (const float4*)&xsT[(Ff - 1) * XS_PITCH];
        #pragma unroll
        for (int i4 = 0; i4 < 8; i4++) {
            float4 xv = xr[i4];
            acc0[i4 * 4 + 0] = fmaf(xv.x, cw0, acc0[i4 * 4 + 0]);
            acc1[i4 * 4 + 0] = fmaf(xv.x, cw1, acc1[i4 * 4 + 0]);
            acc0[i4 * 4 + 1] = fmaf(xv.y, cw0, acc0[i4 * 4 + 1]);
            acc1[i4 * 4 + 1] = fmaf(xv.y, cw1, acc1[i4 * 4 + 1]);
            acc0[i4 * 4 + 2] = fmaf(xv.z, cw0, acc0[i4 * 4 + 2]);
            acc1[i4 * 4 + 2] = fmaf(xv.z, cw1, acc1[i4 * 4 + 2]);
            acc0[i4 * 4 + 3] = fmaf(xv.w, cw0, acc0[i4 * 4 + 3]);
            acc1[i4 * 4 + 3] = fmaf(xv.w, cw1, acc1[i4 * 4 + 3]);
        }
    }
    #pragma unroll
    for (int i = 0; i < 32; i++) {
        size_t zb = (size_t)(m0 + i) * Dm;
        g_z[zb + t] = acc0[i]; g_z[zb + t + 256] = acc1[i];
        size_t cbse = (size_t)(m0 + i) * KTOT;
        g_zc[cbse + t]       = __float2half_rn(acc0[i]);
        g_zc[cbse + t + 256] = __float2half_rn(acc1[i]);
    }
}

// ===== kernel 2: HMMA distance GEMM (fp16 acc), 128-thr CTA, 2 CTAs/SM =====
__device__ __forceinline__ void load_stage(int gg, uint32_t sb, int t,
                                           int m0, int split) {
    const int ch = gg >> 3;
    const int st = gg & 7;
    const int d0 = st * KSTG;
    const int c0 = split * CODES_SPLIT + ch * NCHUNK;
    const uint32_t aB = sb, bB = sb + A_BYTES;
    #pragma unroll
    for (int i = 0; i < 8; i++) {
        int li = t + i * 128, row = li >> 3, c = li & 7;
        uint32_t sw = (uint32_t)(row * 128) + (uint32_t)(((c ^ (row & 7)) << 4));
        CP_ASYNC16(aB + sw, g_zc + (size_t)(m0 + row) * KTOT + d0 + c * 8);
    }
    #pragma unroll
    for (int i = 0; i < 8; i++) {
        int li = t + i * 128, row = li >> 3, c = li & 7;
        uint32_t sw = (uint32_t)(row * 128) + (uint32_t)(((c ^ (row & 7)) << 4));
        CP_ASYNC16(bB + sw, g_e16 + (size_t)(c0 + row) * Dm + d0 + c * 8);
    }
    CP_COMMIT();
}

__global__ __launch_bounds__(128, 2) void k_mma() {
    extern __shared__ __align__(16) char smem[];
    const uint32_t sb = smem_u32(smem);

    const int t = threadIdx.x;
    const int l = t & 31, wid = t >> 5;
    const int wm = wid & 1, wn = wid >> 1;       // 2 x 2 warp grid
    const int m0 = blockIdx.x * 128;
    const int split = blockIdx.y;
    const int l7 = l & 7, hi = (l >> 4) & 1, l15 = l & 15;

    uint32_t aBase[4], bBase[4];
    #pragma unroll
    for (int g4 = 0; g4 < 4; g4++) {
        aBase[g4] = (uint32_t)((wm * 64 + g4 * 16 + l15) * 128);
        bBase[g4] = (uint32_t)((wn * 64 + g4 * 16 + l15) * 128);
    }

    load_stage(0, sb + 0 * STAGE_BYTES, t, m0, split);
    load_stage(1, sb + 1 * STAGE_BYTES, t, m0, split);

    const float INF = __int_as_float(0x7f800000);
    float r1s[8], r2s[8]; int r1k[8], r2k[8];
    #pragma unroll
    for (int i = 0; i < 8; i++) { r1s[i] = INF; r2s[i] = INF; r1k[i] = 0x7fffffff; r2k[i] = 0x7fffffff; }

    int bufC = 0, bufP = 2;
    for (int ch = 0; ch < CHUNKS; ch++) {
        // fp16 accumulators: [mt][nt] -> 2 b32 regs, each packing 2 halfs
        uint32_t acc[4][8][2];
        #pragma unroll
        for (int mt = 0; mt < 4; mt++)
            #pragma unroll
            for (int nt = 0; nt < 8; nt++) { acc[mt][nt][0] = 0u; acc[mt][nt][1] = 0u; }

        for (int st = 0; st < STG_CHUNK; st++) {
            const int g = ch * STG_CHUNK + st;
            if (g == G_TOT - 1) CP_WAIT0(); else CP_WAIT1();
            __syncthreads();
            if (g + 2 < G_TOT)
                load_stage(g + 2, sb + (uint32_t)bufP * STAGE_BYTES, t, m0, split);

            const uint32_t aO = sb + (uint32_t)bufC * STAGE_BYTES;
            const uint32_t bO = aO + A_BYTES;
            #pragma unroll
            for (int ks = 0; ks < 4; ks++) {
                const uint32_t xv = (uint32_t)((((ks * 2) + hi) ^ l7) << 4);
                uint32_t a[4][4], b[4][4];
                #pragma unroll
                for (int g4 = 0; g4 < 4; g4++)
                    LDSM4(a[g4][0], a[g4][1], a[g4][2], a[g4][3], aO + aBase[g4] + xv);
                #pragma unroll
                for (int g4 = 0; g4 < 4; g4++)
                    LDSM4(b[g4][0], b[g4][1], b[g4][2], b[g4][3], bO + bBase[g4] + xv);
                #pragma unroll
                for (int mt = 0; mt < 4; mt++)
                    #pragma unroll
                    for (int p = 0; p < 4; p++) {
                        MMA16816H(acc[mt][2 * p],     a[mt][0], a[mt][1], a[mt][2], a[mt][3],
                                  b[p][0], b[p][2]);
                        MMA16816H(acc[mt][2 * p + 1], a[mt][0], a[mt][1], a[mt][2], a[mt][3],
                                  b[p][1], b[p][3]);
                    }
            }
            bufC = (bufC == 2) ? 0 : bufC + 1;
            bufP = (bufP == 2) ? 0 : bufP + 1;
        }

        // chunk epilogue: unpack half2, score = e2 - 2*dot, running top-2
        const int cb0 = split * CODES_SPLIT + ch * NCHUNK + wn * 64 + (l & 3) * 2;
        #pragma unroll
        for (int mt = 0; mt < 4; mt++) {
            #pragma unroll
            for (int h = 0; h < 2; h++) {      // h=0: rows r, h=1: rows r+8
                const int ri = mt * 2 + h;
                #pragma unroll
                for (int nt = 0; nt < 8; nt++) {
                    int k0 = cb0 + nt * 8;
                    float2 dv = __half22float2(*(__half2*)&acc[mt][nt][h]);
                    float e20 = g_e2[k0], e21 = g_e2[k0 + 1];
                    float s0 = fmaf(-2.f, dv.x, e20);
                    float s1 = fmaf(-2.f, dv.y, e21);
                    top2_upd(r1s[ri], r1k[ri], r2s[ri], r2k[ri], s0, k0);
                    top2_upd(r1s[ri], r1k[ri], r2s[ri], r2k[ri], s1, k0 + 1);
                }
            }
        }
    }

    // ---- final merge: 16 values per token row -> top-2 candidates ----
    __syncthreads();
    float* sS = (float*)smem;                 // [128][16] floats (8 KB)
    int*   sK = (int*)(smem + 128 * 16 * 4);  // [128][16] ints  (8 KB)
    const int slot = (wn * 4 + (l & 3)) * 2;
    #pragma unroll
    for (int mt = 0; mt < 4; mt++) {
        #pragma unroll
        for (int h = 0; h < 2; h++) {
            int ri = mt * 2 + h;
            int row = wm * 64 + mt * 16 + h * 8 + (l >> 2);
            sS[row * 16 + slot]     = r1s[ri];
            sS[row * 16 + slot + 1] = r2s[ri];
            sK[row * 16 + slot]     = r1k[ri];
            sK[row * 16 + slot + 1] = r2k[ri];
        }
    }
    __syncthreads();
    {
        float b1 = INF, b2 = INF; int i1 = 0x7fffffff, i2 = 0x7fffffff;
        #pragma unroll
        for (int j = 0; j < 16; j++) {
            float s = sS[t * 16 + j]; int k = sK[t * 16 + j];
            top2_upd(b1, i1, b2, i2, s, k);
        }
        g_cand[((size_t)split * M_TOK + m0 + t) * NCAND + 0] = i1;
        g_cand[((size_t)split * M_TOK + m0 + t) * NCAND + 1] = i2;
    }
}

// ===== kernel 3: exact recheck of 8, gather, out, loss (+final write) =====
__global__ __launch_bounds__(256) void k_out(const float* __restrict__ cb,
                                             const float* __restrict__ pos,
                                             float* __restrict__ out,
                                             int out_size) {
    const int m = blockIdx.x, t = threadIdx.x;
    const int w = t >> 5, lane = t & 31;
    __shared__ int scand[8];
    __shared__ float sdot[8];
    __shared__ int sBest;
    __shared__ float red[8];

    if (t < 8)
        scand[t] = g_cand[((size_t)(t >> 1) * M_TOK + m) * NCAND + (t & 1)];
    __syncthreads();

    const float* zr = g_z + (size_t)m * Dm;
    const int cidx = scand[w];
    const float* cr = cb + (size_t)cidx * Dm;
    float p = 0.f;
    #pragma unroll
    for (int i = 0; i < 4; i++) {
        int d = lane * 4 + i * 128;
        float4 zv = *(const float4*)&zr[d];
        float4 cv = *(const float4*)&cr[d];
        p = fmaf(zv.x, cv.x, p);
        p = fmaf(zv.y, cv.y, p);
        p = fmaf(zv.z, cv.z, p);
        p = fmaf(zv.w, cv.w, p);
    }
    #pragma unroll
    for (int o = 16; o; o >>= 1) p += __shfl_xor_sync(0xffffffffu, p, o);
    if (lane == 0) sdot[w] = p;
    __syncthreads();

    if (t == 0) {
        float bsc = 3.4e38f; int bi = 0x7fffffff;
        #pragma unroll
        for (int q = 0; q < 8; q++) {
            int k = scand[q];
            float sc = fmaf(-2.f, sdot[q], g_e2[k]);
            if (sc < bsc || (sc == bsc && k < bi)) { bsc = sc; bi = k; }
        }
        sBest = bi;
    }
    __syncthreads();

    const int idx = sBest;
    const float* q  = cb  + (size_t)idx * Dm;
    const float* pr = pos + (m & (Cc - 1)) * Dm;
    float lsum = 0.f;
    #pragma unroll
    for (int r = 0; r < 2; r++) {
        int d = t + r * 256;
        float qv = q[d], zv = zr[d];
        out[(size_t)m * Dm + d] = qv + pr[d];
        float df = qv - zv;
        lsum = fmaf(df, df, lsum);
    }
    #pragma unroll
    for (int o = 16; o; o >>= 1) lsum += __shfl_xor_sync(0xffffffffu, lsum, o);
    if (lane == 0) red[w] = lsum;
    __syncthreads();
    if (t == 0) {
        float s = 0.f;
        #pragma unroll
        for (int ww = 0; ww < 8; ww++) s += red[ww];
        atomicAdd(&g_loss, s);
        __threadfence();
        unsigned prev = atomicAdd(&g_done, 1u);
        if (prev == (unsigned)(M_TOK - 1)) {
            float total = atomicAdd(&g_loss, 0.f);
            if (out_size > M_TOK * Dm)
                out[M_TOK * Dm] = total * (1.f / (float)((long)M_TOK * Dm));
            g_done = 0u;
        }
    }
}

// ===== launcher =====
extern "C" void kernel_launch(void* const* d_in, const int* in_sizes, int n_in,
                              void* d_out, int out_size) {
    const float* x   = (const float*)d_in[0];
    const float* W   = (const float*)d_in[1];
    const float* b   = (const float*)d_in[2];
    const float* cb  = (const float*)d_in[3];
    const float* pos = (const float*)d_in[4];
    float* out = (float*)d_out;

    cudaFuncSetAttribute(k_mma, cudaFuncAttributeMaxDynamicSharedMemorySize, SMEM_SZ);

    k_prep_z<<<1024 + M_TOK / 32, 256>>>(x, W, b, cb);
    k_mma   <<<dim3(M_TOK / 128, NSPLIT), 128, SMEM_SZ>>>();
    k_out   <<<M_TOK, 256>>>(cb, pos, out, out_size);
}

// round 17
// speedup vs baseline: 2.4525x; 1.0360x over previous
#include <cuda_runtime.h>
#include <cuda_fp16.h>
#include <cstdint>
#include <cstddef>

#define M_TOK 8192
#define Dm    512
#define Kcb   8192
#define Ff    129
#define Cc    64

// ---- MMA kernel geometry: 128-thread CTAs, 2 CTAs/SM ----
#define NSPLIT      4
#define CODES_SPLIT (Kcb / NSPLIT)      // 2048
#define NCHUNK      128                 // codes per chunk
#define CHUNKS      (CODES_SPLIT / NCHUNK) // 16
#define KTOT        512                 // fp16 z depth
#define KSTG        64                  // fp16 per stage
#define STG_CHUNK   (KTOT / KSTG)       // 8
#define G_TOT       (CHUNKS * STG_CHUNK)// 128
#define A_BYTES     16384               // 128 x 64 halfs
#define B_BYTES     16384               // 128 x 64 halfs
#define STAGE_BYTES (A_BYTES + B_BYTES) // 32768
#define SMEM_SZ     (3 * STAGE_BYTES)   // 98304 (2 CTAs/SM -> 192KB)
#define NCAND       2                   // top-2 per split, 4 splits -> 8 rechecked

// ---- zgemm geometry: 16 tokens per block for occupancy ----
#define ZTOK        16
#define ZBLOCKS     (M_TOK / ZTOK)      // 512
#define XS_PITCH    20                  // 16 tokens + pad (80B rows, 16B aligned)

// ---- scratch ----
__device__ float  g_z[M_TOK * Dm];
__device__ __align__(16) __half g_zc[M_TOK * KTOT];
__device__ __align__(16) __half g_e16[Kcb * Dm];
__device__ float  g_e2[Kcb];
__device__ int    g_cand[NSPLIT * M_TOK * NCAND];
__device__ float  g_loss;
__device__ unsigned g_done;

// ---- PTX helpers (generic sm_80-class; valid under compute_103) ----
__device__ __forceinline__ uint32_t smem_u32(const void* p) {
    uint32_t r;
    asm("{ .reg .u64 t; cvta.to.shared.u64 t, %1; cvt.u32.u64 %0, t; }" : "=r"(r) : "l"(p));
    return r;
}
#define CP_ASYNC16(dst, src) \
    asm volatile("cp.async.cg.shared.global [%0], [%1], 16;" :: "r"(dst), "l"(src))
#define CP_COMMIT() asm volatile("cp.async.commit_group;" ::: "memory")
#define CP_WAIT0()  asm volatile("cp.async.wait_group 0;" ::: "memory")
#define CP_WAIT1()  asm volatile("cp.async.wait_group 1;" ::: "memory")

#define LDSM4(r0, r1, r2, r3, a) \
    asm volatile("ldmatrix.sync.aligned.m8n8.x4.shared.b16 {%0,%1,%2,%3}, [%4];" \
        : "=r"(r0), "=r"(r1), "=r"(r2), "=r"(r3) : "r"(a))

// fp16-accumulator MMA: D(f16x2 regs)[16x8] += A[16x16] * B[8x16]
#define MMA16816H(d, a0, a1, a2, a3, b0, b1) \
    asm volatile("mma.sync.aligned.m16n8k16.row.col.f16.f16.f16.f16 " \
        "{%0,%1}, {%2,%3,%4,%5}, {%6,%7}, {%0,%1};" \
        : "+r"((d)[0]), "+r"((d)[1]) \
        : "r"(a0), "r"(a1), "r"(a2), "r"(a3), "r"(b0), "r"(b1))

// hot-path top-2: no index tie-break (exact recheck re-applies reference
// tie-break on the candidate set; equal-score near-minima land in (s1,s2)).
__device__ __forceinline__ void top2_upd(float& s1, int& k1, float& s2, int& k2,
                                         float s, int k) {
    if (s < s1) { s2 = s1; k2 = k1; s1 = s; k1 = k; }
    else if (s < s2) { s2 = s; k2 = k; }
}

// ===== kernel 1 (fused): codebook prep (blocks 0..1023) + zgemm (1024..1535) =====
__global__ __launch_bounds__(256) void k_prep_z(const float* __restrict__ x,
                                                const float* __restrict__ W,
                                                const float* __restrict__ b,
                                                const float* __restrict__ cb) {
    __shared__ float xsT[Ff * XS_PITCH];   // transposed x tile: [f][token]
    if (blockIdx.x < 1024) {
        // ---- prep: e2 + fp16 codebook (vectorized) ----
        int row  = blockIdx.x * 8 + (threadIdx.x >> 5);
        int lane = threadIdx.x & 31;
        const float* r = cb + (size_t)row * Dm;
        float s = 0.f;
        #pragma unroll
        for (int i = lane * 4; i < Dm; i += 128) {
            float4 v = *(const float4*)&r[i];
            __half2 h01 = __floats2half2_rn(v.x, v.y);
            __half2 h23 = __floats2half2_rn(v.z, v.w);
            uint2 pk;
            pk.x = *(const uint32_t*)&h01;
            pk.y = *(const uint32_t*)&h23;
            *(uint2*)&g_e16[(size_t)row * Dm + i] = pk;
            s = fmaf(v.x, v.x, s); s = fmaf(v.y, v.y, s);
            s = fmaf(v.z, v.z, s); s = fmaf(v.w, v.w, s);
        }
        #pragma unroll
        for (int o = 16; o; o >>= 1) s += __shfl_xor_sync(0xffffffffu, s, o);
        if (lane == 0) g_e2[row] = s;
        if (blockIdx.x == 0 && threadIdx.x == 0) { g_loss = 0.f; g_done = 0u; }
        return;
    }
    // ---- zgemm: z = x @ W + b, 16 tokens/block, W 4-deep ring ----
    const int m0 = (blockIdx.x - 1024) * ZTOK;
    const int t  = threadIdx.x;

    {
        const int r = t >> 4;               // token 0..15
        for (int c = (t & 15); c < Ff; c += 16)
            xsT[c * XS_PITCH + r] = x[(m0 + r) * Ff + c];
    }
    __syncthreads();

    float acc0[ZTOK], acc1[ZTOK];
    const float b0 = b[t], b1 = b[t + 256];
    #pragma unroll
    for (int i = 0; i < ZTOK; i++) { acc0[i] = b0; acc1[i] = b1; }

    float w0[4], w1[4];
    #pragma unroll
    for (int j = 0; j < 4; j++) {
        w0[j] = W[j * Dm + t];
        w1[j] = W[j * Dm + t + 256];
    }

    for (int f0 = 0; f0 < Ff - 1; f0 += 4) {      // f = 0..127
        #pragma unroll
        for (int j = 0; j < 4; j++) {
            const int f = f0 + j;
            const float cw0 = w0[j], cw1 = w1[j];
            const int fn = f + 4;
            if (fn < Ff) {                        // prefetch 4 ahead
                w0[j] = W[fn * Dm + t];
                w1[j] = W[fn * Dm + t + 256];
            }
            const float4* xr = (const float4*)&xsT[f * XS_PITCH];
            #pragma unroll
            for (int i4 = 0; i4 < 4; i4++) {
                float4 xv = xr[i4];
                acc0[i4 * 4 + 0] = fmaf(xv.x, cw0, acc0[i4 * 4 + 0]);
                acc1[i4 * 4 + 0] = fmaf(xv.x, cw1, acc1[i4 * 4 + 0]);
                acc0[i4 * 4 + 1] = fmaf(xv.y, cw0, acc0[i4 * 4 + 1]);
                acc1[i4 * 4 + 1] = fmaf(xv.y, cw1, acc1[i4 * 4 + 1]);
                acc0[i4 * 4 + 2] = fmaf(xv.z, cw0, acc0[i4 * 4 + 2]);
                acc1[i4 * 4 + 2] = fmaf(xv.z, cw1, acc1[i4 * 4 + 2]);
                acc0[i4 * 4 + 3] = fmaf(xv.w, cw0, acc0[i4 * 4 + 3]);
                acc1[i4 * 4 + 3] = fmaf(xv.w, cw1, acc1[i4 * 4 + 3]);
            }
        }
    }
    {   // tail f = 128 (prefetched into ring slot 0)
        const float cw0 = w0[0], cw1 = w1[0];
        const float4* xr = (const float4*)&xsT[(Ff - 1) * XS_PITCH];
        #pragma unroll
        for (int i4 = 0; i4 < 4; i4++) {
            float4 xv = xr[i4];
            acc0[i4 * 4 + 0] = fmaf(xv.x, cw0, acc0[i4 * 4 + 0]);
            acc1[i4 * 4 + 0] = fmaf(xv.x, cw1, acc1[i4 * 4 + 0]);
            acc0[i4 * 4 + 1] = fmaf(xv.y, cw0, acc0[i4 * 4 + 1]);
            acc1[i4 * 4 + 1] = fmaf(xv.y, cw1, acc1[i4 * 4 + 1]);
            acc0[i4 * 4 + 2] = fmaf(xv.z, cw0, acc0[i4 * 4 + 2]);
            acc1[i4 * 4 + 2] = fmaf(xv.z, cw1, acc1[i4 * 4 + 2]);
            acc0[i4 * 4 + 3] = fmaf(xv.w, cw0, acc0[i4 * 4 + 3]);
            acc1[i4 * 4 + 3] = fmaf(xv.w, cw1, acc1[i4 * 4 + 3]);
        }
    }
    #pragma unroll
    for (int i = 0; i < ZTOK; i++) {
        size_t zb = (size_t)(m0 + i) * Dm;
        g_z[zb + t] = acc0[i]; g_z[zb + t + 256] = acc1[i];
        size_t cbse = (size_t)(m0 + i) * KTOT;
        g_zc[cbse + t]       = __float2half_rn(acc0[i]);
        g_zc[cbse + t + 256] = __float2half_rn(acc1[i]);
    }
}

// ===== kernel 2: HMMA distance GEMM (fp16 acc), 128-thr CTA, 2 CTAs/SM =====
__device__ __forceinline__ void load_stage(int gg, uint32_t sb, int t,
                                           int m0, int split) {
    const int ch = gg >> 3;
    const int st = gg & 7;
    const int d0 = st * KSTG;
    const int c0 = split * CODES_SPLIT + ch * NCHUNK;
    const uint32_t aB = sb, bB = sb + A_BYTES;
    #pragma unroll
    for (int i = 0; i < 8; i++) {
        int li = t + i * 128, row = li >> 3, c = li & 7;
        uint32_t sw = (uint32_t)(row * 128) + (uint32_t)(((c ^ (row & 7)) << 4));
        CP_ASYNC16(aB + sw, g_zc + (size_t)(m0 + row) * KTOT + d0 + c * 8);
    }
    #pragma unroll
    for (int i = 0; i < 8; i++) {
        int li = t + i * 128, row = li >> 3, c = li & 7;
        uint32_t sw = (uint32_t)(row * 128) + (uint32_t)(((c ^ (row & 7)) << 4));
        CP_ASYNC16(bB + sw, g_e16 + (size_t)(c0 + row) * Dm + d0 + c * 8);
    }
    CP_COMMIT();
}

__global__ __launch_bounds__(128, 2) void k_mma() {
    extern __shared__ __align__(16) char smem[];
    const uint32_t sb = smem_u32(smem);

    const int t = threadIdx.x;
    const int l = t & 31, wid = t >> 5;
    const int wm = wid & 1, wn = wid >> 1;       // 2 x 2 warp grid
    const int m0 = blockIdx.x * 128;
    const int split = blockIdx.y;
    const int l7 = l & 7, hi = (l >> 4) & 1, l15 = l & 15;

    uint32_t aBase[4], bBase[4];
    #pragma unroll
    for (int g4 = 0; g4 < 4; g4++) {
        aBase[g4] = (uint32_t)((wm * 64 + g4 * 16 + l15) * 128);
        bBase[g4] = (uint32_t)((wn * 64 + g4 * 16 + l15) * 128);
    }

    load_stage(0, sb + 0 * STAGE_BYTES, t, m0, split);
    load_stage(1, sb + 1 * STAGE_BYTES, t, m0, split);

    const float INF = __int_as_float(0x7f800000);
    float r1s[8], r2s[8]; int r1k[8], r2k[8];
    #pragma unroll
    for (int i = 0; i < 8; i++) { r1s[i] = INF; r2s[i] = INF; r1k[i] = 0x7fffffff; r2k[i] = 0x7fffffff; }

    int bufC = 0, bufP = 2;
    for (int ch = 0; ch < CHUNKS; ch++) {
        // fp16 accumulators: [mt][nt] -> 2 b32 regs, each packing 2 halfs
        uint32_t acc[4][8][2];
        #pragma unroll
        for (int mt = 0; mt < 4; mt++)
            #pragma unroll
            for (int nt = 0; nt < 8; nt++) { acc[mt][nt][0] = 0u; acc[mt][nt][1] = 0u; }

        for (int st = 0; st < STG_CHUNK; st++) {
            const int g = ch * STG_CHUNK + st;
            if (g == G_TOT - 1) CP_WAIT0(); else CP_WAIT1();
            __syncthreads();
            if (g + 2 < G_TOT)
                load_stage(g + 2, sb + (uint32_t)bufP * STAGE_BYTES, t, m0, split);

            const uint32_t aO = sb + (uint32_t)bufC * STAGE_BYTES;
            const uint32_t bO = aO + A_BYTES;
            #pragma unroll
            for (int ks = 0; ks < 4; ks++) {
                const uint32_t xv = (uint32_t)((((ks * 2) + hi) ^ l7) << 4);
                uint32_t a[4][4], b[4][4];
                #pragma unroll
                for (int g4 = 0; g4 < 4; g4++)
                    LDSM4(a[g4][0], a[g4][1], a[g4][2], a[g4][3], aO + aBase[g4] + xv);
                #pragma unroll
                for (int g4 = 0; g4 < 4; g4++)
                    LDSM4(b[g4][0], b[g4][1], b[g4][2], b[g4][3], bO + bBase[g4] + xv);
                #pragma unroll
                for (int mt = 0; mt < 4; mt++)
                    #pragma unroll
                    for (int p = 0; p < 4; p++) {
                        MMA16816H(acc[mt][2 * p],     a[mt][0], a[mt][1], a[mt][2], a[mt][3],
                                  b[p][0], b[p][2]);
                        MMA16816H(acc[mt][2 * p + 1], a[mt][0], a[mt][1], a[mt][2], a[mt][3],
                                  b[p][1], b[p][3]);
                    }
            }
            bufC = (bufC == 2) ? 0 : bufC + 1;
            bufP = (bufP == 2) ? 0 : bufP + 1;
        }

        // chunk epilogue: unpack half2, score = e2 - 2*dot, running top-2
        const int cb0 = split * CODES_SPLIT + ch * NCHUNK + wn * 64 + (l & 3) * 2;
        #pragma unroll
        for (int mt = 0; mt < 4; mt++) {
            #pragma unroll
            for (int h = 0; h < 2; h++) {      // h=0: rows r, h=1: rows r+8
                const int ri = mt * 2 + h;
                #pragma unroll
                for (int nt = 0; nt < 8; nt++) {
                    int k0 = cb0 + nt * 8;
                    float2 dv = __half22float2(*(__half2*)&acc[mt][nt][h]);
                    float e20 = g_e2[k0], e21 = g_e2[k0 + 1];
                    float s0 = fmaf(-2.f, dv.x, e20);
                    float s1 = fmaf(-2.f, dv.y, e21);
                    top2_upd(r1s[ri], r1k[ri], r2s[ri], r2k[ri], s0, k0);
                    top2_upd(r1s[ri], r1k[ri], r2s[ri], r2k[ri], s1, k0 + 1);
                }
            }
        }
    }

    // ---- final merge: 16 values per token row -> top-2 candidates ----
    __syncthreads();
    float* sS = (float*)smem;                 // [128][16] floats (8 KB)
    int*   sK = (int*)(smem + 128 * 16 * 4);  // [128][16] ints  (8 KB)
    const int slot = (wn * 4 + (l & 3)) * 2;
    #pragma unroll
    for (int mt = 0; mt < 4; mt++) {
        #pragma unroll
        for (int h = 0; h < 2; h++) {
            int ri = mt * 2 + h;
            int row = wm * 64 + mt * 16 + h * 8 + (l >> 2);
            sS[row * 16 + slot]     = r1s[ri];
            sS[row * 16 + slot + 1] = r2s[ri];
            sK[row * 16 + slot]     = r1k[ri];
            sK[row * 16 + slot + 1] = r2k[ri];
        }
    }
    __syncthreads();
    {
        float b1 = INF, b2 = INF; int i1 = 0x7fffffff, i2 = 0x7fffffff;
        #pragma unroll
        for (int j = 0; j < 16; j++) {
            float s = sS[t * 16 + j]; int k = sK[t * 16 + j];
            top2_upd(b1, i1, b2, i2, s, k);
        }
        g_cand[((size_t)split * M_TOK + m0 + t) * NCAND + 0] = i1;
        g_cand[((size_t)split * M_TOK + m0 + t) * NCAND + 1] = i2;
    }
}

// ===== kernel 3: exact recheck of 8, gather, out, loss (+final write) =====
// 128 threads: warp w handles candidates 2w and 2w+1 (z row shared).
__global__ __launch_bounds__(128) void k_out(const float* __restrict__ cb,
                                             const float* __restrict__ pos,
                                             float* __restrict__ out,
                                             int out_size) {
    const int m = blockIdx.x, t = threadIdx.x;
    const int w = t >> 5, lane = t & 31;
    __shared__ int scand[8];
    __shared__ float sdot[8];
    __shared__ int sBest;
    __shared__ float red[4];

    if (t < 8)
        scand[t] = g_cand[((size_t)(t >> 1) * M_TOK + m) * NCAND + (t & 1)];
    __syncthreads();

    const float* zr = g_z + (size_t)m * Dm;
    const int c0 = scand[2 * w], c1 = scand[2 * w + 1];
    const float* cr0 = cb + (size_t)c0 * Dm;
    const float* cr1 = cb + (size_t)c1 * Dm;
    float p0 = 0.f, p1 = 0.f;
    #pragma unroll
    for (int i = 0; i < 4; i++) {
        int d = lane * 4 + i * 128;
        float4 zv = *(const float4*)&zr[d];
        float4 a  = *(const float4*)&cr0[d];
        float4 bb = *(const float4*)&cr1[d];
        p0 = fmaf(zv.x, a.x, p0);  p1 = fmaf(zv.x, bb.x, p1);
        p0 = fmaf(zv.y, a.y, p0);  p1 = fmaf(zv.y, bb.y, p1);
        p0 = fmaf(zv.z, a.z, p0);  p1 = fmaf(zv.z, bb.z, p1);
        p0 = fmaf(zv.w, a.w, p0);  p1 = fmaf(zv.w, bb.w, p1);
    }
    #pragma unroll
    for (int o = 16; o; o >>= 1) {
        p0 += __shfl_xor_sync(0xffffffffu, p0, o);
        p1 += __shfl_xor_sync(0xffffffffu, p1, o);
    }
    if (lane == 0) { sdot[2 * w] = p0; sdot[2 * w + 1] = p1; }
    __syncthreads();

    if (t == 0) {
        float bsc = 3.4e38f; int bi = 0x7fffffff;
        #pragma unroll
        for (int q = 0; q < 8; q++) {
            int k = scand[q];
            float sc = fmaf(-2.f, sdot[q], g_e2[k]);
            if (sc < bsc || (sc == bsc && k < bi)) { bsc = sc; bi = k; }
        }
        sBest = bi;
    }
    __syncthreads();

    const int idx = sBest;
    const float* q  = cb  + (size_t)idx * Dm;
    const float* pr = pos + (m & (Cc - 1)) * Dm;
    float lsum = 0.f;
    {
        int d = t * 4;
        float4 qv = *(const float4*)&q[d];
        float4 zv = *(const float4*)&zr[d];
        float4 pv = *(const float4*)&pr[d];
        float4 ov;
        ov.x = qv.x + pv.x; ov.y = qv.y + pv.y;
        ov.z = qv.z + pv.z; ov.w = qv.w + pv.w;
        *(float4*)&out[(size_t)m * Dm + d] = ov;
        float d0 = qv.x - zv.x, d1 = qv.y - zv.y;
        float d2 = qv.z - zv.z, d3 = qv.w - zv.w;
        lsum = fmaf(d0, d0, fmaf(d1, d1, fmaf(d2, d2, d3 * d3)));
    }
    #pragma unroll
    for (int o = 16; o; o >>= 1) lsum += __shfl_xor_sync(0xffffffffu, lsum, o);
    if (lane == 0) red[w] = lsum;
    __syncthreads();
    if (t == 0) {
        float s = red[0] + red[1] + red[2] + red[3];
        atomicAdd(&g_loss, s);
        __threadfence();
        unsigned prev = atomicAdd(&g_done, 1u);
        if (prev == (unsigned)(M_TOK - 1)) {
            float total = atomicAdd(&g_loss, 0.f);
            if (out_size > M_TOK * Dm)
                out[M_TOK * Dm] = total * (1.f / (float)((long)M_TOK * Dm));
            g_done = 0u;
        }
    }
}

// ===== launcher =====
extern "C" void kernel_launch(void* const* d_in, const int* in_sizes, int n_in,
                              void* d_out, int out_size) {
    const float* x   = (const float*)d_in[0];
    const float* W   = (const float*)d_in[1];
    const float* b   = (const float*)d_in[2];
    const float* cb  = (const float*)d_in[3];
    const float* pos = (const float*)d_in[4];
    float* out = (float*)d_out;

    cudaFuncSetAttribute(k_mma, cudaFuncAttributeMaxDynamicSharedMemorySize, SMEM_SZ);

    k_prep_z<<<1024 + ZBLOCKS, 256>>>(x, W, b, cb);
    k_mma   <<<dim3(M_TOK / 128, NSPLIT), 128, SMEM_SZ>>>();
    k_out   <<<M_TOK, 128>>>(cb, pos, out, out_size);
}